// round 9
// baseline (speedup 1.0000x reference)
#include <cuda_runtime.h>
#include <cuda_bf16.h>

#define Bb 256
#define Tt 512
#define Ff 128
#define Uu 1024
#define N4 4096

typedef __nv_bfloat16 bf;

// ---------------- scratch (static device globals; no allocation) -------------
__device__ bf g_h0h[Bb * Uu]; __device__ bf g_h0l[Bb * Uu];
__device__ bf g_h1h[Bb * Uu]; __device__ bf g_h1l[Bb * Uu];
__device__ bf g_hsh[(size_t)Tt * Bb * Uu]; __device__ bf g_hsl[(size_t)Tt * Bb * Uu];
__device__ bf g_t1h[(size_t)Tt * Bb * Uu]; __device__ bf g_t1l[(size_t)Tt * Bb * Uu];
__device__ bf g_xh[(size_t)Bb * Tt * Ff];  __device__ bf g_xl[(size_t)Bb * Tt * Ff];
// weights transposed to [n][k] and split hi/lo
__device__ bf g_whTh[(size_t)N4 * Uu]; __device__ bf g_whTl[(size_t)N4 * Uu];
__device__ bf g_wdTh[(size_t)N4 * Uu]; __device__ bf g_wdTl[(size_t)N4 * Uu];
__device__ bf g_wxTh[(size_t)N4 * Ff]; __device__ bf g_wxTl[(size_t)N4 * Ff];
__device__ bf g_d1Th[(size_t)Uu * Uu]; __device__ bf g_d1Tl[(size_t)Uu * Uu];
__device__ bf g_d2Th[(size_t)Ff * Uu]; __device__ bf g_d2Tl[(size_t)Ff * Uu];
__device__ unsigned int g_bar;

// ---------------- helpers ----------------------------------------------------
__device__ __forceinline__ void split_bf(float v, bf& hi, bf& lo) {
    hi = __float2bfloat16_rn(v);
    lo = __float2bfloat16_rn(v - __bfloat162float(hi));
}

__device__ __forceinline__ void mma16(float c[4], const unsigned int a[4],
                                      const unsigned int b[2]) {
    asm volatile(
        "mma.sync.aligned.m16n8k16.row.col.f32.bf16.bf16.f32 "
        "{%0,%1,%2,%3}, {%4,%5,%6,%7}, {%8,%9}, {%0,%1,%2,%3};"
        : "+f"(c[0]), "+f"(c[1]), "+f"(c[2]), "+f"(c[3])
        : "r"(a[0]), "r"(a[1]), "r"(a[2]), "r"(a[3]), "r"(b[0]), "r"(b[1]));
}

__device__ __forceinline__ float sigmoidf_(float x) {
    return 1.f / (1.f + __expf(-x));
}

__device__ __forceinline__ void cpa16(void* s, const void* g) {
    // cg: bypass L1 — required: persistent kernel, h re-read across steps.
    unsigned int sa = (unsigned int)__cvta_generic_to_shared(s);
    asm volatile("cp.async.cg.shared.global [%0], [%1], 16;" :: "r"(sa), "l"(g));
}

// ---------------- prep: split to bf16 hi/lo, transpose weights ---------------
__global__ void __launch_bounds__(256) prep_kernel(
        const float* __restrict__ x,
        const float* __restrict__ ewx, const float* __restrict__ ewh,
        const float* __restrict__ dwx, const float* __restrict__ dwh,
        const float* __restrict__ d1w, const float* __restrict__ d2w) {
    int i = blockIdx.x * blockDim.x + threadIdx.x;
    if (i == 0) g_bar = 0u;
    if (i < Bb * Tt * Ff) split_bf(x[i], g_xh[i], g_xl[i]);
    if (i < N4 * Uu) {                     // i = k*4096 + n  (coalesced reads)
        int k = i >> 12, n = i & 4095;
        size_t o = (size_t)n * Uu + k;
        split_bf(ewh[i],          g_whTh[o], g_whTl[o]);
        split_bf(dwx[i] + dwh[i], g_wdTh[o], g_wdTl[o]);
    }
    if (i < N4 * Ff) {                     // i = k*4096 + n, k < 128
        int k = i >> 12, n = i & 4095;
        size_t o = (size_t)n * Ff + k;
        split_bf(ewx[i], g_wxTh[o], g_wxTl[o]);
    }
    if (i < Uu * Uu) {                     // i = k*1024 + n
        int k = i >> 10, n = i & 1023;
        size_t o = (size_t)n * Uu + k;
        split_bf(d1w[i], g_d1Th[o], g_d1Tl[o]);
    }
    if (i < Uu * Ff) {                     // i = k*128 + n
        int k = i >> 7, n = i & 127;
        size_t o = (size_t)n * Uu + k;
        split_bf(d2w[i], g_d2Th[o], g_d2Tl[o]);
    }
    if (i < Bb * Uu) {
        g_h0h[i] = __float2bfloat16(0.f); g_h0l[i] = __float2bfloat16(0.f);
    }
}

// ---------------- persistent recurrence kernel --------------------------------
// 128 CTAs (32 u-tiles x 4 m-tiles), 256 threads, grid barrier between steps.
// bf16x3: z = Ah@Bh + Al@Bh + Ah@Bl, fp32 accum. 4-stage cp.async ring.
struct SmP {
    bf Ah[4][64][40];                      // 20480 B (80B rows: bank-conflict-free)
    bf Al[4][64][40];                      // 20480 B
    union {
        struct { bf Bh[4][128][40]; bf Bl[4][128][40]; } b;   // 81920 B
        float Z[64][132];                  // 33792 B (aliases B; used post-GEMM)
    } u;
};
#define SMEMP_BYTES (sizeof(SmP))

__device__ __forceinline__ void prefetch_tiles(SmP* sm, int st,
        const bf* Ah, const bf* Al, int lda,
        const bf* Bh, const bf* Bl, int ldb, int u0, int tid) {
    {   // A: 64 rows x 32 halves = 64B/row = 4 x 16B
        int row = tid >> 2, seg = (tid & 3) * 8;
        cpa16(&sm->Ah[st][row][seg], Ah + (size_t)row * lda + seg);
        cpa16(&sm->Al[st][row][seg], Al + (size_t)row * lda + seg);
    }
#pragma unroll
    for (int s = 0; s < 2; s++) {          // B: 128 n-rows x 32 halves
        int idx = tid + s * 256;
        int nn = idx >> 2, seg = (idx & 3) * 8;
        int g = ((nn >> 5) << 10) + u0 + (nn & 31);   // gate*1024 + u
        cpa16(&sm->u.b.Bh[st][nn][seg], Bh + (size_t)g * ldb + seg);
        cpa16(&sm->u.b.Bl[st][nn][seg], Bl + (size_t)g * ldb + seg);
    }
    asm volatile("cp.async.commit_group;");
}

__global__ void __launch_bounds__(256) lstm_persist(const float* __restrict__ eb,
                                                    const float* __restrict__ db) {
    extern __shared__ char smraw[];
    SmP* sm = (SmP*)smraw;
    const int u0 = blockIdx.x * 32;
    const int m0 = blockIdx.y * 64;
    const int tid = threadIdx.x, lane = tid & 31, wid = tid >> 5;
    const int wm = wid >> 2, wn = wid & 3, r = lane >> 2, q = lane & 3;

    float c_reg[8];                        // cell state lives in registers: the
#pragma unroll                             // CTA<->(m,u) tile map is fixed for
    for (int s = 0; s < 8; s++) c_reg[s] = 0.f;   // all 1024 steps.

    for (int t = 0; t < 2 * Tt; t++) {
        const int is_dec = (t >= Tt);
        const bf *hih, *hil;
        bf *hoh, *hol;
        const bf *Wh, *Wl;
        const float* bias;
        int NC, ts;
        if (is_dec) {
            ts = t - Tt;
            Wh = g_wdTh; Wl = g_wdTl; bias = db; NC = 32;
            if (ts == 0) { hih = g_h0h; hil = g_h0l; }
            else { hih = g_hsh + (size_t)(ts - 1) * Bb * Uu;
                   hil = g_hsl + (size_t)(ts - 1) * Bb * Uu; }
            hoh = g_hsh + (size_t)ts * Bb * Uu;
            hol = g_hsl + (size_t)ts * Bb * Uu;
        } else {
            ts = t;
            Wh = g_whTh; Wl = g_whTl; bias = eb; NC = 36;  // 32 h + 4 x chunks
            if (ts & 1) { hih = g_h1h; hil = g_h1l; hoh = g_h0h; hol = g_h0l; }
            else        { hih = g_h0h; hil = g_h0l; hoh = g_h1h; hol = g_h1l; }
        }

        float acc[2][4][4];
#pragma unroll
        for (int a = 0; a < 2; a++)
#pragma unroll
            for (int b = 0; b < 4; b++)
#pragma unroll
                for (int e = 0; e < 4; e++) acc[a][b][e] = 0.f;

        auto getAB = [&](int c, const bf*& Ah_, const bf*& Al_, int& lda,
                         const bf*& Bh_, const bf*& Bl_, int& ldb) {
            if (c < 32) {
                Ah_ = hih + (size_t)m0 * Uu + c * 32;
                Al_ = hil + (size_t)m0 * Uu + c * 32;
                lda = Uu;
                Bh_ = Wh + c * 32; Bl_ = Wl + c * 32; ldb = Uu;
            } else {
                int cc = c - 32;
                size_t off = (size_t)m0 * (Tt * Ff) + (size_t)ts * Ff + cc * 32;
                Ah_ = g_xh + off; Al_ = g_xl + off; lda = Tt * Ff;
                Bh_ = g_wxTh + cc * 32; Bl_ = g_wxTl + cc * 32; ldb = Ff;
            }
        };

        // prologue: fill 3 stages (NC >= 32 > 3 always)
#pragma unroll
        for (int p = 0; p < 3; p++) {
            const bf *Ah_, *Al_, *Bh_, *Bl_; int lda, ldb;
            getAB(p, Ah_, Al_, lda, Bh_, Bl_, ldb);
            prefetch_tiles(sm, p, Ah_, Al_, lda, Bh_, Bl_, ldb, u0, tid);
        }

        for (int c = 0; c < NC; c++) {
            asm volatile("cp.async.wait_group 2;");   // group c done (1 group/chunk)
            __syncthreads();
            if (c + 3 < NC) {
                const bf *Ah_, *Al_, *Bh_, *Bl_; int lda, ldb;
                getAB(c + 3, Ah_, Al_, lda, Bh_, Bl_, ldb);
                prefetch_tiles(sm, (c + 3) & 3, Ah_, Al_, lda, Bh_, Bl_, ldb, u0, tid);
            } else {
                asm volatile("cp.async.commit_group;");   // empty: keep group==chunk
            }
            const int st = c & 3;
#pragma unroll
            for (int kh = 0; kh < 2; kh++) {
                const int kb = kh * 16;
                unsigned int ah[2][4], al[2][4], bh[4][2], bl[4][2];
#pragma unroll
                for (int mb = 0; mb < 2; mb++) {
                    int row = wm * 32 + mb * 16;
                    ah[mb][0] = *(const unsigned int*)&sm->Ah[st][row + r    ][kb + 2 * q];
                    ah[mb][1] = *(const unsigned int*)&sm->Ah[st][row + r + 8][kb + 2 * q];
                    ah[mb][2] = *(const unsigned int*)&sm->Ah[st][row + r    ][kb + 2 * q + 8];
                    ah[mb][3] = *(const unsigned int*)&sm->Ah[st][row + r + 8][kb + 2 * q + 8];
                    al[mb][0] = *(const unsigned int*)&sm->Al[st][row + r    ][kb + 2 * q];
                    al[mb][1] = *(const unsigned int*)&sm->Al[st][row + r + 8][kb + 2 * q];
                    al[mb][2] = *(const unsigned int*)&sm->Al[st][row + r    ][kb + 2 * q + 8];
                    al[mb][3] = *(const unsigned int*)&sm->Al[st][row + r + 8][kb + 2 * q + 8];
                }
#pragma unroll
                for (int nb = 0; nb < 4; nb++) {
                    int col = wn * 32 + nb * 8 + r;
                    bh[nb][0] = *(const unsigned int*)&sm->u.b.Bh[st][col][kb + 2 * q];
                    bh[nb][1] = *(const unsigned int*)&sm->u.b.Bh[st][col][kb + 2 * q + 8];
                    bl[nb][0] = *(const unsigned int*)&sm->u.b.Bl[st][col][kb + 2 * q];
                    bl[nb][1] = *(const unsigned int*)&sm->u.b.Bl[st][col][kb + 2 * q + 8];
                }
                // pass-outer ordering: same per-accumulator sequence (hh,lh,hl)
                // as before => numerics identical; reuse distance 2 -> 8 mma.
#pragma unroll
                for (int nb = 0; nb < 4; nb++) {
                    mma16(acc[0][nb], ah[0], bh[nb]);
                    mma16(acc[1][nb], ah[1], bh[nb]);
                }
#pragma unroll
                for (int nb = 0; nb < 4; nb++) {
                    mma16(acc[0][nb], al[0], bh[nb]);
                    mma16(acc[1][nb], al[1], bh[nb]);
                }
#pragma unroll
                for (int nb = 0; nb < 4; nb++) {
                    mma16(acc[0][nb], ah[0], bl[nb]);
                    mma16(acc[1][nb], ah[1], bl[nb]);
                }
            }
        }
        asm volatile("cp.async.wait_group 0;");
        __syncthreads();                   // all compute done before Z aliases B

        // stage z through smem so each thread gathers all 4 gates of one (b,u)
#pragma unroll
        for (int mb = 0; mb < 2; mb++)
#pragma unroll
            for (int nb = 0; nb < 4; nb++) {
                int row = wm * 32 + mb * 16 + r;
                int col = wn * 32 + nb * 8 + 2 * q;
                sm->u.Z[row    ][col    ] = acc[mb][nb][0];
                sm->u.Z[row    ][col + 1] = acc[mb][nb][1];
                sm->u.Z[row + 8][col    ] = acc[mb][nb][2];
                sm->u.Z[row + 8][col + 1] = acc[mb][nb][3];
            }
        __syncthreads();

#pragma unroll
        for (int s = 0; s < 8; s++) {
            int idx = tid + s * 256;
            int i = idx >> 5, j = idx & 31;
            int u = u0 + j;
            float zi = sm->u.Z[i][j     ] + bias[u];
            float zf = sm->u.Z[i][j + 32] + bias[u + 1024];
            float zg = sm->u.Z[i][j + 64] + bias[u + 2048];
            float zo = sm->u.Z[i][j + 96] + bias[u + 3072];
            float ig = sigmoidf_(zi);
            float fg = sigmoidf_(zf);
            float gg = tanhf(zg);
            float og = sigmoidf_(zo);
            float cn = fg * c_reg[s] + ig * gg;
            c_reg[s] = cn;
            float h = og * tanhf(cn);
            size_t gi = (size_t)(m0 + i) * Uu + u;
            split_bf(h, hoh[gi], hol[gi]);
        }

        // -------- grid barrier: 128 CTAs all co-resident (1 wave on 148 SMs) --
        __syncthreads();
        if (tid == 0) {
            __threadfence();
            atomicAdd(&g_bar, 1u);
            unsigned int target = 128u * (unsigned int)(t + 1);
            while (*((volatile unsigned int*)&g_bar) < target) __nanosleep(64);
            __threadfence();
        }
        __syncthreads();
    }
}

// ---------------- dense epilogue GEMMs (bf16x3) -------------------------------
// SRC==0: t1 = split(relu(hs @ d1W + d1b)), N=1024
// SRC==1: out =          t1 @ d2W + d2b   , N=128, store permuted [T,B]->[B,T]
template <int SRC>
__global__ void __launch_bounds__(256) dense_kernel(const float* __restrict__ bias,
                                                    float* __restrict__ outp) {
    const bf* Agh = (SRC == 0) ? g_hsh : g_t1h;
    const bf* Agl = (SRC == 0) ? g_hsl : g_t1l;
    const bf* Bgh = (SRC == 0) ? g_d1Th : g_d2Th;
    const bf* Bgl = (SRC == 0) ? g_d1Tl : g_d2Tl;
    __shared__ bf Ash[64][40], Asl[64][40], Bsh[64][40], Bsl[64][40];
    const int n0 = blockIdx.x * 64;
    const int m0 = blockIdx.y * 64;
    const int tid = threadIdx.x, lane = tid & 31, wid = tid >> 5;
    const int wm = wid >> 2, wn = wid & 3, r = lane >> 2, q = lane & 3;

    float acc[2][2][4];
#pragma unroll
    for (int a = 0; a < 2; a++)
#pragma unroll
        for (int b = 0; b < 2; b++)
#pragma unroll
            for (int e = 0; e < 4; e++) acc[a][b][e] = 0.f;

    const int row = tid >> 2, seg = (tid & 3) * 8;
    for (int k0 = 0; k0 < 1024; k0 += 32) {
        __syncthreads();
        *(uint4*)&Ash[row][seg] = *(const uint4*)(Agh + (size_t)(m0 + row) * 1024 + k0 + seg);
        *(uint4*)&Asl[row][seg] = *(const uint4*)(Agl + (size_t)(m0 + row) * 1024 + k0 + seg);
        *(uint4*)&Bsh[row][seg] = *(const uint4*)(Bgh + (size_t)(n0 + row) * 1024 + k0 + seg);
        *(uint4*)&Bsl[row][seg] = *(const uint4*)(Bgl + (size_t)(n0 + row) * 1024 + k0 + seg);
        __syncthreads();
#pragma unroll
        for (int kh = 0; kh < 2; kh++) {
            const int kb = kh * 16;
            unsigned int ah[2][4], al[2][4], bh[2][2], bl[2][2];
#pragma unroll
            for (int mb = 0; mb < 2; mb++) {
                int rw = wm * 32 + mb * 16;
                ah[mb][0] = *(const unsigned int*)&Ash[rw + r    ][kb + 2 * q];
                ah[mb][1] = *(const unsigned int*)&Ash[rw + r + 8][kb + 2 * q];
                ah[mb][2] = *(const unsigned int*)&Ash[rw + r    ][kb + 2 * q + 8];
                ah[mb][3] = *(const unsigned int*)&Ash[rw + r + 8][kb + 2 * q + 8];
                al[mb][0] = *(const unsigned int*)&Asl[rw + r    ][kb + 2 * q];
                al[mb][1] = *(const unsigned int*)&Asl[rw + r + 8][kb + 2 * q];
                al[mb][2] = *(const unsigned int*)&Asl[rw + r    ][kb + 2 * q + 8];
                al[mb][3] = *(const unsigned int*)&Asl[rw + r + 8][kb + 2 * q + 8];
            }
#pragma unroll
            for (int nb = 0; nb < 2; nb++) {
                int col = wn * 16 + nb * 8 + r;
                bh[nb][0] = *(const unsigned int*)&Bsh[col][kb + 2 * q];
                bh[nb][1] = *(const unsigned int*)&Bsh[col][kb + 2 * q + 8];
                bl[nb][0] = *(const unsigned int*)&Bsl[col][kb + 2 * q];
                bl[nb][1] = *(const unsigned int*)&Bsl[col][kb + 2 * q + 8];
            }
#pragma unroll
            for (int nb = 0; nb < 2; nb++) {
                mma16(acc[0][nb], ah[0], bh[nb]);
                mma16(acc[1][nb], ah[1], bh[nb]);
            }
#pragma unroll
            for (int nb = 0; nb < 2; nb++) {
                mma16(acc[0][nb], al[0], bh[nb]);
                mma16(acc[1][nb], al[1], bh[nb]);
            }
#pragma unroll
            for (int nb = 0; nb < 2; nb++) {
                mma16(acc[0][nb], ah[0], bl[nb]);
                mma16(acc[1][nb], ah[1], bl[nb]);
            }
        }
    }

#pragma unroll
    for (int mb = 0; mb < 2; mb++)
#pragma unroll
        for (int nb = 0; nb < 2; nb++) {
            int rwb = m0 + wm * 32 + mb * 16 + r;
            int cwb = n0 + wn * 16 + nb * 8 + 2 * q;
#pragma unroll
            for (int e = 0; e < 4; e++) {
                int rr = rwb + (e >> 1) * 8;
                int cc = cwb + (e & 1);
                float v = acc[mb][nb][e] + bias[cc];
                if (SRC == 0) {
                    v = fmaxf(v, 0.f);
                    size_t o = (size_t)rr * 1024 + cc;
                    split_bf(v, g_t1h[o], g_t1l[o]);
                } else {
                    int tt = rr >> 8, bb = rr & 255;   // row = t*256 + b
                    outp[((size_t)bb * Tt + tt) * Ff + cc] = v;
                }
            }
        }
}

// ---------------- launch ------------------------------------------------------
extern "C" void kernel_launch(void* const* d_in, const int* in_sizes, int n_in,
                              void* d_out, int out_size) {
    const float* x   = (const float*)d_in[0];
    const float* ewx = (const float*)d_in[1];
    const float* ewh = (const float*)d_in[2];
    const float* eb  = (const float*)d_in[3];
    const float* dwx = (const float*)d_in[4];
    const float* dwh = (const float*)d_in[5];
    const float* db  = (const float*)d_in[6];
    const float* d1w = (const float*)d_in[7];
    const float* d1b = (const float*)d_in[8];
    const float* d2w = (const float*)d_in[9];
    const float* d2b = (const float*)d_in[10];
    float* out = (float*)d_out;

    cudaFuncSetAttribute(lstm_persist, cudaFuncAttributeMaxDynamicSharedMemorySize,
                         (int)SMEMP_BYTES);

    prep_kernel<<<(Bb * Tt * Ff + 255) / 256, 256>>>(x, ewx, ewh, dwx, dwh, d1w, d2w);

    dim3 sgrid(Uu / 32, Bb / 64);   // 128 CTAs: single wave on 148 SMs
    lstm_persist<<<sgrid, 256, SMEMP_BYTES>>>(eb, db);

    dense_kernel<0><<<dim3(1024 / 64, (Tt * Bb) / 64), 256>>>(d1b, nullptr);
    dense_kernel<1><<<dim3(128 / 64, (Tt * Bb) / 64), 256>>>(d2b, out);
}

// round 11
// speedup vs baseline: 1.1091x; 1.1091x over previous
#include <cuda_runtime.h>
#include <cuda_bf16.h>

#define Bb 256
#define Tt 512
#define Ff 128
#define Uu 1024
#define N4 4096

typedef __nv_bfloat16 bf;

// ---------------- scratch (static device globals; no allocation) -------------
__device__ bf g_h0h[Bb * Uu]; __device__ bf g_h0l[Bb * Uu];
__device__ bf g_h1h[Bb * Uu]; __device__ bf g_h1l[Bb * Uu];
__device__ bf g_hsh[(size_t)Tt * Bb * Uu]; __device__ bf g_hsl[(size_t)Tt * Bb * Uu];
__device__ bf g_t1h[(size_t)Tt * Bb * Uu]; __device__ bf g_t1l[(size_t)Tt * Bb * Uu];
__device__ bf g_xh[(size_t)Bb * Tt * Ff];  __device__ bf g_xl[(size_t)Bb * Tt * Ff];
// weights transposed to [n][k] and split hi/lo
__device__ bf g_whTh[(size_t)N4 * Uu]; __device__ bf g_whTl[(size_t)N4 * Uu];
__device__ bf g_wdTh[(size_t)N4 * Uu]; __device__ bf g_wdTl[(size_t)N4 * Uu];
__device__ bf g_wxTh[(size_t)N4 * Ff]; __device__ bf g_wxTl[(size_t)N4 * Ff];
__device__ bf g_d1Th[(size_t)Uu * Uu]; __device__ bf g_d1Tl[(size_t)Uu * Uu];
__device__ bf g_d2Th[(size_t)Ff * Uu]; __device__ bf g_d2Tl[(size_t)Ff * Uu];
__device__ unsigned int g_bar;

// ---------------- helpers ----------------------------------------------------
__device__ __forceinline__ void split_bf(float v, bf& hi, bf& lo) {
    hi = __float2bfloat16_rn(v);
    lo = __float2bfloat16_rn(v - __bfloat162float(hi));
}
__device__ __forceinline__ void mma16(float c[4], const unsigned int a[4],
                                      const unsigned int b[2]) {
    asm volatile(
        "mma.sync.aligned.m16n8k16.row.col.f32.bf16.bf16.f32 "
        "{%0,%1,%2,%3}, {%4,%5,%6,%7}, {%8,%9}, {%0,%1,%2,%3};"
        : "+f"(c[0]), "+f"(c[1]), "+f"(c[2]), "+f"(c[3])
        : "r"(a[0]), "r"(a[1]), "r"(a[2]), "r"(a[3]), "r"(b[0]), "r"(b[1]));
}
__device__ __forceinline__ void ldm4(unsigned int r[4], unsigned int addr) {
    asm volatile("ldmatrix.sync.aligned.m8n8.x4.shared.b16 {%0,%1,%2,%3}, [%4];"
                 : "=r"(r[0]), "=r"(r[1]), "=r"(r[2]), "=r"(r[3]) : "r"(addr));
}
__device__ __forceinline__ float sigmoidf_(float x) {
    return 1.f / (1.f + __expf(-x));
}
__device__ __forceinline__ void cpa16(unsigned int sa, const void* g) {
    // cg: bypass L1 — required: persistent kernel, h re-read across steps.
    asm volatile("cp.async.cg.shared.global [%0], [%1], 16;" :: "r"(sa), "l"(g));
}

// ---------------- prep: split to bf16 hi/lo, transpose weights ---------------
__global__ void __launch_bounds__(256) prep_kernel(
        const float* __restrict__ x,
        const float* __restrict__ ewx, const float* __restrict__ ewh,
        const float* __restrict__ dwx, const float* __restrict__ dwh,
        const float* __restrict__ d1w, const float* __restrict__ d2w) {
    int i = blockIdx.x * blockDim.x + threadIdx.x;
    if (i == 0) g_bar = 0u;
    if (i < Bb * Tt * Ff) split_bf(x[i], g_xh[i], g_xl[i]);
    if (i < N4 * Uu) {
        int k = i >> 12, n = i & 4095;
        size_t o = (size_t)n * Uu + k;
        split_bf(ewh[i],          g_whTh[o], g_whTl[o]);
        split_bf(dwx[i] + dwh[i], g_wdTh[o], g_wdTl[o]);
    }
    if (i < N4 * Ff) {
        int k = i >> 12, n = i & 4095;
        size_t o = (size_t)n * Ff + k;
        split_bf(ewx[i], g_wxTh[o], g_wxTl[o]);
    }
    if (i < Uu * Uu) {
        int k = i >> 10, n = i & 1023;
        size_t o = (size_t)n * Uu + k;
        split_bf(d1w[i], g_d1Th[o], g_d1Tl[o]);
    }
    if (i < Uu * Ff) {
        int k = i >> 7, n = i & 127;
        size_t o = (size_t)n * Uu + k;
        split_bf(d2w[i], g_d2Th[o], g_d2Tl[o]);
    }
    if (i < Bb * Uu) {
        g_h0h[i] = __float2bfloat16(0.f); g_h0l[i] = __float2bfloat16(0.f);
    }
}

// ---------------- persistent recurrence kernel --------------------------------
// 128 CTAs (32 u-tiles x 4 m-tiles), 256 threads, grid barrier between steps.
// bf16x3: z = Ah@Bh + Al@Bh + Ah@Bl, fp32 accum. 4-stage cp.async ring.
// smem byte offsets (row = 40 bf = 80 B, conflict-free for LDSM)
#define L_AH 0u            // [4][64][40]  stage stride 5120
#define L_AL 20480u
#define L_BH 40960u        // [4][128][40] stage stride 10240
#define L_BL 81920u
#define L_Z  40960u        // Z[64][132] fp32 aliases B region (post-GEMM only)
#define L_TOTAL 122880u

struct SmP {
    bf Ah[4][64][40];
    bf Al[4][64][40];
    union {
        struct { bf Bh[4][128][40]; bf Bl[4][128][40]; } b;
        float Z[64][132];
    } u;
};

__device__ __forceinline__ void prefetch_tiles(SmP* sm, int st,
        const bf* Ah, const bf* Al, size_t lda,
        const bf* Bh, const bf* Bl, size_t ldb, int u0, int tid) {
    unsigned int sb0;
    {   // A: 64 rows x 32 halves = 64B/row = 4 x 16B
        int row = tid >> 2, seg = (tid & 3) * 8;
        sb0 = (unsigned int)__cvta_generic_to_shared(&sm->Ah[st][row][seg]);
        cpa16(sb0, Ah + (size_t)row * lda + seg);
        cpa16(sb0 + 20480u, Al + (size_t)row * lda + seg);
    }
#pragma unroll
    for (int s = 0; s < 2; s++) {          // B: 128 n-rows x 32 halves
        int idx = tid + s * 256;
        int nn = idx >> 2, seg = (idx & 3) * 8;
        size_t grow = (size_t)(((nn >> 5) << 10) + u0 + (nn & 31)) * ldb;
        unsigned int sa = (unsigned int)__cvta_generic_to_shared(&sm->u.b.Bh[st][nn][seg]);
        cpa16(sa, Bh + grow + seg);
        cpa16(sa + 40960u, Bl + grow + seg);
    }
    asm volatile("cp.async.commit_group;");
}

__global__ void __launch_bounds__(256) lstm_persist(const float* __restrict__ eb,
                                                    const float* __restrict__ db) {
    extern __shared__ char smraw[];
    SmP* sm = (SmP*)smraw;
    const unsigned int sb = (unsigned int)__cvta_generic_to_shared(smraw);
    const int u0 = blockIdx.x * 32;
    const int m0 = blockIdx.y * 64;
    const int tid = threadIdx.x, lane = tid & 31, wid = tid >> 5;
    const int wm = wid >> 2, wn = wid & 3, r = lane >> 2, q = lane & 3;

    // ldmatrix per-lane address offsets (bytes, row stride 80B)
    const int arow = wm * 32 + (lane & 7) + ((lane >> 3) & 1) * 8;
    const unsigned int aoff = (unsigned int)(arow * 80 + ((lane >> 4) * 8) * 2);
    const int brow = wn * 32 + (lane & 7) + ((lane >> 4) & 1) * 8;
    const unsigned int boff = (unsigned int)(brow * 80 + (((lane >> 3) & 1) * 8) * 2);

    float c_reg[8];
#pragma unroll
    for (int s = 0; s < 8; s++) c_reg[s] = 0.f;

    for (int t = 0; t < 2 * Tt; t++) {
        const int is_dec = (t >= Tt);
        const bf *hih, *hil; bf *hoh, *hol;
        const bf *Wh, *Wl; const float* bias;
        int NC, ts;
        if (is_dec) {
            ts = t - Tt;
            Wh = g_wdTh; Wl = g_wdTl; bias = db; NC = 32;
            if (ts == 0) { hih = g_h0h; hil = g_h0l; }
            else { hih = g_hsh + (size_t)(ts - 1) * Bb * Uu;
                   hil = g_hsl + (size_t)(ts - 1) * Bb * Uu; }
            hoh = g_hsh + (size_t)ts * Bb * Uu;
            hol = g_hsl + (size_t)ts * Bb * Uu;
        } else {
            ts = t;
            Wh = g_whTh; Wl = g_whTl; bias = eb; NC = 36;  // 32 h + 4 x chunks
            if (ts & 1) { hih = g_h1h; hil = g_h1l; hoh = g_h0h; hol = g_h0l; }
            else        { hih = g_h0h; hil = g_h0l; hoh = g_h1h; hol = g_h1l; }
        }

        float acc[2][4][4];
#pragma unroll
        for (int a = 0; a < 2; a++)
#pragma unroll
            for (int b = 0; b < 4; b++)
#pragma unroll
                for (int e = 0; e < 4; e++) acc[a][b][e] = 0.f;

        auto getAB = [&](int c, const bf*& Ah_, const bf*& Al_, size_t& lda,
                         const bf*& Bh_, const bf*& Bl_, size_t& ldb) {
            if (c < 32) {
                Ah_ = hih + (size_t)m0 * Uu + c * 32;
                Al_ = hil + (size_t)m0 * Uu + c * 32;
                lda = Uu;
                Bh_ = Wh + c * 32; Bl_ = Wl + c * 32; ldb = Uu;
            } else {
                int cc = c - 32;
                size_t off = (size_t)m0 * (Tt * Ff) + (size_t)ts * Ff + cc * 32;
                Ah_ = g_xh + off; Al_ = g_xl + off; lda = (size_t)Tt * Ff;
                Bh_ = g_wxTh + cc * 32; Bl_ = g_wxTl + cc * 32; ldb = Ff;
            }
        };

        // prologue: fill 3 stages
#pragma unroll
        for (int p = 0; p < 3; p++) {
            const bf *Ah_, *Al_, *Bh_, *Bl_; size_t lda, ldb;
            getAB(p, Ah_, Al_, lda, Bh_, Bl_, ldb);
            prefetch_tiles(sm, p, Ah_, Al_, lda, Bh_, Bl_, ldb, u0, tid);
        }

        for (int c = 0; c < NC; c++) {
            asm volatile("cp.async.wait_group 2;");   // group c complete
            __syncthreads();
            if (c + 3 < NC) {
                const bf *Ah_, *Al_, *Bh_, *Bl_; size_t lda, ldb;
                getAB(c + 3, Ah_, Al_, lda, Bh_, Bl_, ldb);
                prefetch_tiles(sm, (c + 3) & 3, Ah_, Al_, lda, Bh_, Bl_, ldb, u0, tid);
            } else {
                asm volatile("cp.async.commit_group;");   // keep group==chunk
            }
            const int st = c & 3;
            const unsigned int aH = sb + L_AH + st * 5120u + aoff;
            const unsigned int aL = sb + L_AL + st * 5120u + aoff;
            const unsigned int bH = sb + L_BH + st * 10240u + boff;
            const unsigned int bL = sb + L_BL + st * 10240u + boff;

            // register double-buffered fragments across kh
            unsigned int ah[2][2][4], al[2][2][4], bh[2][4][2], bl[2][4][2];
            auto load_frags = [&](int buf, int kb) {
#pragma unroll
                for (int mb = 0; mb < 2; mb++) {
                    ldm4(ah[buf][mb], aH + mb * 1280u + kb * 2);
                    ldm4(al[buf][mb], aL + mb * 1280u + kb * 2);
                }
#pragma unroll
                for (int pr = 0; pr < 2; pr++) {
                    unsigned int tmp[4];
                    ldm4(tmp, bH + pr * 1280u + kb * 2);
                    bh[buf][pr * 2][0] = tmp[0]; bh[buf][pr * 2][1] = tmp[1];
                    bh[buf][pr * 2 + 1][0] = tmp[2]; bh[buf][pr * 2 + 1][1] = tmp[3];
                    ldm4(tmp, bL + pr * 1280u + kb * 2);
                    bl[buf][pr * 2][0] = tmp[0]; bl[buf][pr * 2][1] = tmp[1];
                    bl[buf][pr * 2 + 1][0] = tmp[2]; bl[buf][pr * 2 + 1][1] = tmp[3];
                }
            };
            load_frags(0, 0);
#pragma unroll
            for (int kh = 0; kh < 2; kh++) {
                if (kh == 0) load_frags(1, 16);    // prefetch next kh under mma
                // per-accumulator order hh,lh,hl — numerics identical to R9
#pragma unroll
                for (int nb = 0; nb < 4; nb++) {
                    mma16(acc[0][nb], ah[kh][0], bh[kh][nb]);
                    mma16(acc[1][nb], ah[kh][1], bh[kh][nb]);
                }
#pragma unroll
                for (int nb = 0; nb < 4; nb++) {
                    mma16(acc[0][nb], al[kh][0], bh[kh][nb]);
                    mma16(acc[1][nb], al[kh][1], bh[kh][nb]);
                }
#pragma unroll
                for (int nb = 0; nb < 4; nb++) {
                    mma16(acc[0][nb], ah[kh][0], bl[kh][nb]);
                    mma16(acc[1][nb], ah[kh][1], bl[kh][nb]);
                }
            }
        }
        asm volatile("cp.async.wait_group 0;");
        __syncthreads();                   // all compute done before Z aliases B

        // stage z through smem so each thread gathers all 4 gates of one (b,u)
#pragma unroll
        for (int mb = 0; mb < 2; mb++)
#pragma unroll
            for (int nb = 0; nb < 4; nb++) {
                int row = wm * 32 + mb * 16 + r;
                int col = wn * 32 + nb * 8 + 2 * q;
                sm->u.Z[row    ][col    ] = acc[mb][nb][0];
                sm->u.Z[row    ][col + 1] = acc[mb][nb][1];
                sm->u.Z[row + 8][col    ] = acc[mb][nb][2];
                sm->u.Z[row + 8][col + 1] = acc[mb][nb][3];
            }
        __syncthreads();

#pragma unroll
        for (int s = 0; s < 8; s++) {
            int idx = tid + s * 256;
            int i = idx >> 5, j = idx & 31;
            int u = u0 + j;
            float zi = sm->u.Z[i][j     ] + bias[u];
            float zf = sm->u.Z[i][j + 32] + bias[u + 1024];
            float zg = sm->u.Z[i][j + 64] + bias[u + 2048];
            float zo = sm->u.Z[i][j + 96] + bias[u + 3072];
            float ig = sigmoidf_(zi);
            float fg = sigmoidf_(zf);
            float gg = tanhf(zg);
            float og = sigmoidf_(zo);
            float cn = fg * c_reg[s] + ig * gg;
            c_reg[s] = cn;
            float h = og * tanhf(cn);
            size_t gi = (size_t)(m0 + i) * Uu + u;
            split_bf(h, hoh[gi], hol[gi]);
        }

        // -------- grid barrier: 128 CTAs all co-resident (1 wave on 148 SMs) --
        __syncthreads();
        if (tid == 0) {
            __threadfence();
            atomicAdd(&g_bar, 1u);
            unsigned int target = 128u * (unsigned int)(t + 1);
            while (*((volatile unsigned int*)&g_bar) < target) __nanosleep(64);
            __threadfence();
        }
        __syncthreads();
    }
}

// ---------------- dense epilogue GEMMs (bf16x3, ldmatrix + cp.async ring) -----
// SRC==0: t1 = split(relu(hs @ d1W + d1b)), N=1024
// SRC==1: out =          t1 @ d2W + d2b   , N=128, store permuted [T,B]->[B,T]
// smem: 3-stage ring, each stage Ah/Al/Bh/Bl = [64][40] bf (5120B)
#define D_AH 0u
#define D_AL 15360u
#define D_BH 30720u
#define D_BL 46080u
#define D_TOTAL 61440u

template <int SRC>
__global__ void __launch_bounds__(256) dense_kernel(const float* __restrict__ bias,
                                                    float* __restrict__ outp) {
    const bf* Agh = (SRC == 0) ? g_hsh : g_t1h;
    const bf* Agl = (SRC == 0) ? g_hsl : g_t1l;
    const bf* Bgh = (SRC == 0) ? g_d1Th : g_d2Th;
    const bf* Bgl = (SRC == 0) ? g_d1Tl : g_d2Tl;
    extern __shared__ char smraw[];
    const unsigned int sb = (unsigned int)__cvta_generic_to_shared(smraw);
    const int n0 = blockIdx.x * 64;
    const int m0 = blockIdx.y * 64;
    const int tid = threadIdx.x, lane = tid & 31, wid = tid >> 5;
    const int wm = wid >> 2, wn = wid & 3, r = lane >> 2, q = lane & 3;

    const int arow = wm * 32 + (lane & 7) + ((lane >> 3) & 1) * 8;
    const unsigned int aoff = (unsigned int)(arow * 80 + ((lane >> 4) * 8) * 2);
    const int brow = wn * 16 + (lane & 7) + ((lane >> 4) & 1) * 8;
    const unsigned int boff = (unsigned int)(brow * 80 + (((lane >> 3) & 1) * 8) * 2);

    float acc[2][2][4];
#pragma unroll
    for (int a = 0; a < 2; a++)
#pragma unroll
        for (int b = 0; b < 2; b++)
#pragma unroll
            for (int e = 0; e < 4; e++) acc[a][b][e] = 0.f;

    const int frow = tid >> 2, fseg = (tid & 3) * 8;
    auto fill = [&](int st, int c) {
        unsigned int sa = sb + st * 5120u + (unsigned int)(frow * 80 + fseg * 2);
        size_t ga = (size_t)(m0 + frow) * 1024 + c * 32 + fseg;
        size_t gb = (size_t)(n0 + frow) * 1024 + c * 32 + fseg;
        cpa16(sa + D_AH, Agh + ga);
        cpa16(sa + D_AL, Agl + ga);
        cpa16(sa + D_BH, Bgh + gb);
        cpa16(sa + D_BL, Bgl + gb);
        asm volatile("cp.async.commit_group;");
    };

    fill(0, 0); fill(1, 1);
    for (int c = 0; c < 32; c++) {
        asm volatile("cp.async.wait_group 1;");
        __syncthreads();
        if (c + 2 < 32) fill((c + 2) % 3, c + 2);
        else asm volatile("cp.async.commit_group;");

        const int st = c % 3;
        const unsigned int aH = sb + st * 5120u + D_AH + aoff;
        const unsigned int aL = sb + st * 5120u + D_AL + aoff;
        const unsigned int bH = sb + st * 5120u + D_BH + boff;
        const unsigned int bL = sb + st * 5120u + D_BL + boff;

        unsigned int ah[2][2][4], al[2][2][4], bh[2][2][2], bl[2][2][2];
        auto load_frags = [&](int buf, int kb) {
#pragma unroll
            for (int mb = 0; mb < 2; mb++) {
                ldm4(ah[buf][mb], aH + mb * 1280u + kb * 2);
                ldm4(al[buf][mb], aL + mb * 1280u + kb * 2);
            }
            unsigned int tmp[4];
            ldm4(tmp, bH + kb * 2);
            bh[buf][0][0] = tmp[0]; bh[buf][0][1] = tmp[1];
            bh[buf][1][0] = tmp[2]; bh[buf][1][1] = tmp[3];
            ldm4(tmp, bL + kb * 2);
            bl[buf][0][0] = tmp[0]; bl[buf][0][1] = tmp[1];
            bl[buf][1][0] = tmp[2]; bl[buf][1][1] = tmp[3];
        };
        load_frags(0, 0);
#pragma unroll
        for (int kh = 0; kh < 2; kh++) {
            if (kh == 0) load_frags(1, 16);
#pragma unroll
            for (int nb = 0; nb < 2; nb++) {
                mma16(acc[0][nb], ah[kh][0], bh[kh][nb]);
                mma16(acc[1][nb], ah[kh][1], bh[kh][nb]);
            }
#pragma unroll
            for (int nb = 0; nb < 2; nb++) {
                mma16(acc[0][nb], al[kh][0], bh[kh][nb]);
                mma16(acc[1][nb], al[kh][1], bh[kh][nb]);
            }
#pragma unroll
            for (int nb = 0; nb < 2; nb++) {
                mma16(acc[0][nb], ah[kh][0], bl[kh][nb]);
                mma16(acc[1][nb], ah[kh][1], bl[kh][nb]);
            }
        }
        __syncthreads();    // stage consumed; safe for refill next iteration
    }
    asm volatile("cp.async.wait_group 0;");

#pragma unroll
    for (int mb = 0; mb < 2; mb++)
#pragma unroll
        for (int nb = 0; nb < 2; nb++) {
            int rwb = m0 + wm * 32 + mb * 16 + r;
            int cwb = n0 + wn * 16 + nb * 8 + 2 * q;
#pragma unroll
            for (int e = 0; e < 4; e++) {
                int rr = rwb + (e >> 1) * 8;
                int cc = cwb + (e & 1);
                float v = acc[mb][nb][e] + bias[cc];
                if (SRC == 0) {
                    v = fmaxf(v, 0.f);
                    size_t o = (size_t)rr * 1024 + cc;
                    split_bf(v, g_t1h[o], g_t1l[o]);
                } else {
                    int tt = rr >> 8, bb = rr & 255;   // row = t*256 + b
                    outp[((size_t)bb * Tt + tt) * Ff + cc] = v;
                }
            }
        }
}

// ---------------- launch ------------------------------------------------------
extern "C" void kernel_launch(void* const* d_in, const int* in_sizes, int n_in,
                              void* d_out, int out_size) {
    const float* x   = (const float*)d_in[0];
    const float* ewx = (const float*)d_in[1];
    const float* ewh = (const float*)d_in[2];
    const float* eb  = (const float*)d_in[3];
    const float* dwx = (const float*)d_in[4];
    const float* dwh = (const float*)d_in[5];
    const float* db  = (const float*)d_in[6];
    const float* d1w = (const float*)d_in[7];
    const float* d1b = (const float*)d_in[8];
    const float* d2w = (const float*)d_in[9];
    const float* d2b = (const float*)d_in[10];
    float* out = (float*)d_out;

    cudaFuncSetAttribute(lstm_persist, cudaFuncAttributeMaxDynamicSharedMemorySize,
                         (int)L_TOTAL);
    cudaFuncSetAttribute(dense_kernel<0>, cudaFuncAttributeMaxDynamicSharedMemorySize,
                         (int)D_TOTAL);
    cudaFuncSetAttribute(dense_kernel<1>, cudaFuncAttributeMaxDynamicSharedMemorySize,
                         (int)D_TOTAL);

    prep_kernel<<<(Bb * Tt * Ff + 255) / 256, 256>>>(x, ewx, ewh, dwx, dwh, d1w, d2w);

    dim3 sgrid(Uu / 32, Bb / 64);   // 128 CTAs: single wave on 148 SMs
    lstm_persist<<<sgrid, 256, L_TOTAL>>>(eb, db);

    dense_kernel<0><<<dim3(1024 / 64, (Tt * Bb) / 64), 256, D_TOTAL>>>(d1b, nullptr);
    dense_kernel<1><<<dim3(128 / 64, (Tt * Bb) / 64), 256, D_TOTAL>>>(d2b, out);
}

// round 12
// speedup vs baseline: 1.1256x; 1.0148x over previous
#include <cuda_runtime.h>
#include <cuda_bf16.h>

#define Bb 256
#define Tt 512
#define Ff 128
#define Uu 1024
#define N4 4096

typedef __nv_bfloat16 bf;

// ---------------- scratch (static device globals; no allocation) -------------
__device__ bf g_h0h[Bb * Uu]; __device__ bf g_h0l[Bb * Uu];
__device__ bf g_h1h[Bb * Uu]; __device__ bf g_h1l[Bb * Uu];
__device__ bf g_hsh[(size_t)Tt * Bb * Uu]; __device__ bf g_hsl[(size_t)Tt * Bb * Uu];
__device__ bf g_t1h[(size_t)Tt * Bb * Uu]; __device__ bf g_t1l[(size_t)Tt * Bb * Uu];
__device__ bf g_xh[(size_t)Bb * Tt * Ff];  __device__ bf g_xl[(size_t)Bb * Tt * Ff];
// weights transposed to [n][k] and split hi/lo
__device__ bf g_whTh[(size_t)N4 * Uu]; __device__ bf g_whTl[(size_t)N4 * Uu];
__device__ bf g_wdTh[(size_t)N4 * Uu]; __device__ bf g_wdTl[(size_t)N4 * Uu];
__device__ bf g_wxTh[(size_t)N4 * Ff]; __device__ bf g_wxTl[(size_t)N4 * Ff];
__device__ bf g_d1Th[(size_t)Uu * Uu]; __device__ bf g_d1Tl[(size_t)Uu * Uu];
__device__ bf g_d2Th[(size_t)Ff * Uu]; __device__ bf g_d2Tl[(size_t)Ff * Uu];
__device__ unsigned int g_bar;

// ---------------- helpers ----------------------------------------------------
__device__ __forceinline__ void split_bf(float v, bf& hi, bf& lo) {
    hi = __float2bfloat16_rn(v);
    lo = __float2bfloat16_rn(v - __bfloat162float(hi));
}
__device__ __forceinline__ void mma16(float c[4], const unsigned int a[4],
                                      const unsigned int b[2]) {
    asm volatile(
        "mma.sync.aligned.m16n8k16.row.col.f32.bf16.bf16.f32 "
        "{%0,%1,%2,%3}, {%4,%5,%6,%7}, {%8,%9}, {%0,%1,%2,%3};"
        : "+f"(c[0]), "+f"(c[1]), "+f"(c[2]), "+f"(c[3])
        : "r"(a[0]), "r"(a[1]), "r"(a[2]), "r"(a[3]), "r"(b[0]), "r"(b[1]));
}
__device__ __forceinline__ void ldm4(unsigned int r[4], unsigned int addr) {
    asm volatile("ldmatrix.sync.aligned.m8n8.x4.shared.b16 {%0,%1,%2,%3}, [%4];"
                 : "=r"(r[0]), "=r"(r[1]), "=r"(r[2]), "=r"(r[3]) : "r"(addr));
}
__device__ __forceinline__ float sigmoidf_(float x) {
    return 1.f / (1.f + __expf(-x));
}
__device__ __forceinline__ void cpa16(unsigned int sa, const void* g) {
    // cg: bypass L1 — required: persistent kernel, h re-read across steps.
    asm volatile("cp.async.cg.shared.global [%0], [%1], 16;" :: "r"(sa), "l"(g));
}

// ---------------- prep: split to bf16 hi/lo, transpose weights ---------------
__global__ void __launch_bounds__(256) prep_kernel(
        const float* __restrict__ x,
        const float* __restrict__ ewx, const float* __restrict__ ewh,
        const float* __restrict__ dwx, const float* __restrict__ dwh,
        const float* __restrict__ d1w, const float* __restrict__ d2w) {
    int i = blockIdx.x * blockDim.x + threadIdx.x;
    if (i == 0) g_bar = 0u;
    if (i < Bb * Tt * Ff) split_bf(x[i], g_xh[i], g_xl[i]);
    if (i < N4 * Uu) {
        int k = i >> 12, n = i & 4095;
        size_t o = (size_t)n * Uu + k;
        split_bf(ewh[i],          g_whTh[o], g_whTl[o]);
        split_bf(dwx[i] + dwh[i], g_wdTh[o], g_wdTl[o]);
    }
    if (i < N4 * Ff) {
        int k = i >> 12, n = i & 4095;
        size_t o = (size_t)n * Ff + k;
        split_bf(ewx[i], g_wxTh[o], g_wxTl[o]);
    }
    if (i < Uu * Uu) {
        int k = i >> 10, n = i & 1023;
        size_t o = (size_t)n * Uu + k;
        split_bf(d1w[i], g_d1Th[o], g_d1Tl[o]);
    }
    if (i < Uu * Ff) {
        int k = i >> 7, n = i & 127;
        size_t o = (size_t)n * Uu + k;
        split_bf(d2w[i], g_d2Th[o], g_d2Tl[o]);
    }
    if (i < Bb * Uu) {
        g_h0h[i] = __float2bfloat16(0.f); g_h0l[i] = __float2bfloat16(0.f);
    }
}

// ---------------- persistent recurrence kernel --------------------------------
// 128 CTAs (32 u-tiles x 4 m-tiles), 512 threads (16 warps: 2m x 8n, warp tile
// 32x16), grid barrier between steps. bf16x3, fp32 accum, 4-stage cp.async ring.
// smem byte offsets (row = 40 bf = 80 B, conflict-free for LDSM)
#define L_AH 0u            // [4][64][40]  stage stride 5120
#define L_AL 20480u
#define L_BH 40960u        // [4][128][40] stage stride 10240
#define L_BL 81920u
#define L_TOTAL 122880u

struct SmP {
    bf Ah[4][64][40];
    bf Al[4][64][40];
    union {
        struct { bf Bh[4][128][40]; bf Bl[4][128][40]; } b;
        float Z[64][132];
    } u;
};

__device__ __forceinline__ void prefetch_tiles(SmP* sm, int st,
        const bf* Ah, const bf* Al, size_t lda,
        const bf* Bh, const bf* Bl, size_t ldb, int u0, int tid) {
    if (tid < 256) {   // A: 64 rows x 32 halves = 256 x 16B (hi and lo)
        int row = tid >> 2, seg = (tid & 3) * 8;
        unsigned int sa = (unsigned int)__cvta_generic_to_shared(&sm->Ah[st][row][seg]);
        cpa16(sa, Ah + (size_t)row * lda + seg);
        cpa16(sa + 20480u, Al + (size_t)row * lda + seg);
    }
    {   // B: 128 n-rows x 32 halves = 512 x 16B (hi and lo)
        int nn = tid >> 2, seg = (tid & 3) * 8;
        size_t grow = (size_t)(((nn >> 5) << 10) + u0 + (nn & 31)) * ldb;
        unsigned int sa = (unsigned int)__cvta_generic_to_shared(&sm->u.b.Bh[st][nn][seg]);
        cpa16(sa, Bh + grow + seg);
        cpa16(sa + 40960u, Bl + grow + seg);
    }
    asm volatile("cp.async.commit_group;");
}

__global__ void __launch_bounds__(512) lstm_persist(const float* __restrict__ eb,
                                                    const float* __restrict__ db) {
    extern __shared__ char smraw[];
    SmP* sm = (SmP*)smraw;
    const unsigned int sb = (unsigned int)__cvta_generic_to_shared(smraw);
    const int u0 = blockIdx.x * 32;
    const int m0 = blockIdx.y * 64;
    const int tid = threadIdx.x, lane = tid & 31, wid = tid >> 5;
    const int wm = wid >> 3, wn = wid & 7, r = lane >> 2, q = lane & 3;

    // ldmatrix per-lane address offsets (bytes, row stride 80B)
    const int arow = wm * 32 + (lane & 7) + ((lane >> 3) & 1) * 8;
    const unsigned int aoff = (unsigned int)(arow * 80 + (lane >> 4) * 16);
    const int brow = wn * 16 + (lane & 7) + ((lane >> 4) & 1) * 8;
    const unsigned int boff = (unsigned int)(brow * 80 + ((lane >> 3) & 1) * 16);

    float c_reg[4];
#pragma unroll
    for (int s = 0; s < 4; s++) c_reg[s] = 0.f;

    for (int t = 0; t < 2 * Tt; t++) {
        const int is_dec = (t >= Tt);
        const bf *hih, *hil; bf *hoh, *hol;
        const bf *Wh, *Wl; const float* bias;
        int NC, ts;
        if (is_dec) {
            ts = t - Tt;
            Wh = g_wdTh; Wl = g_wdTl; bias = db; NC = 32;
            if (ts == 0) { hih = g_h0h; hil = g_h0l; }
            else { hih = g_hsh + (size_t)(ts - 1) * Bb * Uu;
                   hil = g_hsl + (size_t)(ts - 1) * Bb * Uu; }
            hoh = g_hsh + (size_t)ts * Bb * Uu;
            hol = g_hsl + (size_t)ts * Bb * Uu;
        } else {
            ts = t;
            Wh = g_whTh; Wl = g_whTl; bias = eb; NC = 36;  // 32 h + 4 x chunks
            if (ts & 1) { hih = g_h1h; hil = g_h1l; hoh = g_h0h; hol = g_h0l; }
            else        { hih = g_h0h; hil = g_h0l; hoh = g_h1h; hol = g_h1l; }
        }

        float acc[2][2][4];
#pragma unroll
        for (int a = 0; a < 2; a++)
#pragma unroll
            for (int b = 0; b < 2; b++)
#pragma unroll
                for (int e = 0; e < 4; e++) acc[a][b][e] = 0.f;

        auto getAB = [&](int c, const bf*& Ah_, const bf*& Al_, size_t& lda,
                         const bf*& Bh_, const bf*& Bl_, size_t& ldb) {
            if (c < 32) {
                Ah_ = hih + (size_t)m0 * Uu + c * 32;
                Al_ = hil + (size_t)m0 * Uu + c * 32;
                lda = Uu;
                Bh_ = Wh + c * 32; Bl_ = Wl + c * 32; ldb = Uu;
            } else {
                int cc = c - 32;
                size_t off = (size_t)m0 * (Tt * Ff) + (size_t)ts * Ff + cc * 32;
                Ah_ = g_xh + off; Al_ = g_xl + off; lda = (size_t)Tt * Ff;
                Bh_ = g_wxTh + cc * 32; Bl_ = g_wxTl + cc * 32; ldb = Ff;
            }
        };

        // prologue: fill 3 stages
#pragma unroll
        for (int p = 0; p < 3; p++) {
            const bf *Ah_, *Al_, *Bh_, *Bl_; size_t lda, ldb;
            getAB(p, Ah_, Al_, lda, Bh_, Bl_, ldb);
            prefetch_tiles(sm, p, Ah_, Al_, lda, Bh_, Bl_, ldb, u0, tid);
        }

        for (int c = 0; c < NC; c++) {
            asm volatile("cp.async.wait_group 2;");   // group c complete
            __syncthreads();
            if (c + 3 < NC) {
                const bf *Ah_, *Al_, *Bh_, *Bl_; size_t lda, ldb;
                getAB(c + 3, Ah_, Al_, lda, Bh_, Bl_, ldb);
                prefetch_tiles(sm, (c + 3) & 3, Ah_, Al_, lda, Bh_, Bl_, ldb, u0, tid);
            } else {
                asm volatile("cp.async.commit_group;");   // keep group==chunk
            }
            const int st = c & 3;
            const unsigned int aH = sb + L_AH + st * 5120u + aoff;
            const unsigned int aL = sb + L_AL + st * 5120u + aoff;
            const unsigned int bH = sb + L_BH + st * 10240u + boff;
            const unsigned int bL = sb + L_BL + st * 10240u + boff;

#pragma unroll
            for (int kh = 0; kh < 2; kh++) {
                const int kb = kh * 16;
                unsigned int ah[2][4], al[2][4], bh[2][2], bl[2][2];
#pragma unroll
                for (int mb = 0; mb < 2; mb++) {
                    ldm4(ah[mb], aH + mb * 1280u + kb * 2);
                    ldm4(al[mb], aL + mb * 1280u + kb * 2);
                }
                {
                    unsigned int tmp[4];
                    ldm4(tmp, bH + kb * 2);
                    bh[0][0] = tmp[0]; bh[0][1] = tmp[1];
                    bh[1][0] = tmp[2]; bh[1][1] = tmp[3];
                    ldm4(tmp, bL + kb * 2);
                    bl[0][0] = tmp[0]; bl[0][1] = tmp[1];
                    bl[1][0] = tmp[2]; bl[1][1] = tmp[3];
                }
                // per-accumulator order hh,lh,hl — numerics identical to R11
#pragma unroll
                for (int nb = 0; nb < 2; nb++) {
                    mma16(acc[0][nb], ah[0], bh[nb]);
                    mma16(acc[1][nb], ah[1], bh[nb]);
                }
#pragma unroll
                for (int nb = 0; nb < 2; nb++) {
                    mma16(acc[0][nb], al[0], bh[nb]);
                    mma16(acc[1][nb], al[1], bh[nb]);
                }
#pragma unroll
                for (int nb = 0; nb < 2; nb++) {
                    mma16(acc[0][nb], ah[0], bl[nb]);
                    mma16(acc[1][nb], ah[1], bl[nb]);
                }
            }
        }
        asm volatile("cp.async.wait_group 0;");
        __syncthreads();                   // all compute done before Z aliases B

        // stage z through smem so each thread gathers all 4 gates of one (b,u)
#pragma unroll
        for (int mb = 0; mb < 2; mb++)
#pragma unroll
            for (int nb = 0; nb < 2; nb++) {
                int row = wm * 32 + mb * 16 + r;
                int col = wn * 16 + nb * 8 + 2 * q;
                sm->u.Z[row    ][col    ] = acc[mb][nb][0];
                sm->u.Z[row    ][col + 1] = acc[mb][nb][1];
                sm->u.Z[row + 8][col    ] = acc[mb][nb][2];
                sm->u.Z[row + 8][col + 1] = acc[mb][nb][3];
            }
        __syncthreads();

#pragma unroll
        for (int s = 0; s < 4; s++) {
            int idx = tid + s * 512;
            int i = idx >> 5, j = idx & 31;
            int u = u0 + j;
            float zi = sm->u.Z[i][j     ] + bias[u];
            float zf = sm->u.Z[i][j + 32] + bias[u + 1024];
            float zg = sm->u.Z[i][j + 64] + bias[u + 2048];
            float zo = sm->u.Z[i][j + 96] + bias[u + 3072];
            float ig = sigmoidf_(zi);
            float fg = sigmoidf_(zf);
            float gg = tanhf(zg);
            float og = sigmoidf_(zo);
            float cn = fg * c_reg[s] + ig * gg;
            c_reg[s] = cn;
            float h = og * tanhf(cn);
            size_t gi = (size_t)(m0 + i) * Uu + u;
            split_bf(h, hoh[gi], hol[gi]);
        }

        // -------- grid barrier: 128 CTAs all co-resident (1 wave on 148 SMs) --
        __syncthreads();
        if (tid == 0) {
            __threadfence();
            atomicAdd(&g_bar, 1u);
            unsigned int target = 128u * (unsigned int)(t + 1);
            while (*((volatile unsigned int*)&g_bar) < target) __nanosleep(64);
            __threadfence();
        }
        __syncthreads();
    }
}

// ---------------- dense epilogue GEMMs (bf16x3, ldmatrix + cp.async ring) -----
// SRC==0: t1 = split(relu(hs @ d1W + d1b)), N=1024
// SRC==1: out =          t1 @ d2W + d2b   , N=128, store permuted [T,B]->[B,T]
// smem: 3-stage ring, each stage Ah/Al/Bh/Bl = [64][40] bf (5120B)
#define D_AH 0u
#define D_AL 15360u
#define D_BH 30720u
#define D_BL 46080u
#define D_TOTAL 61440u

template <int SRC>
__global__ void __launch_bounds__(256) dense_kernel(const float* __restrict__ bias,
                                                    float* __restrict__ outp) {
    const bf* Agh = (SRC == 0) ? g_hsh : g_t1h;
    const bf* Agl = (SRC == 0) ? g_hsl : g_t1l;
    const bf* Bgh = (SRC == 0) ? g_d1Th : g_d2Th;
    const bf* Bgl = (SRC == 0) ? g_d1Tl : g_d2Tl;
    extern __shared__ char smraw[];
    const unsigned int sb = (unsigned int)__cvta_generic_to_shared(smraw);
    const int n0 = blockIdx.x * 64;
    const int m0 = blockIdx.y * 64;
    const int tid = threadIdx.x, lane = tid & 31, wid = tid >> 5;
    const int wm = wid >> 2, wn = wid & 3, r = lane >> 2, q = lane & 3;

    const int arow = wm * 32 + (lane & 7) + ((lane >> 3) & 1) * 8;
    const unsigned int aoff = (unsigned int)(arow * 80 + (lane >> 4) * 16);
    const int brow = wn * 16 + (lane & 7) + ((lane >> 4) & 1) * 8;
    const unsigned int boff = (unsigned int)(brow * 80 + ((lane >> 3) & 1) * 16);

    float acc[2][2][4];
#pragma unroll
    for (int a = 0; a < 2; a++)
#pragma unroll
        for (int b = 0; b < 2; b++)
#pragma unroll
            for (int e = 0; e < 4; e++) acc[a][b][e] = 0.f;

    const int frow = tid >> 2, fseg = (tid & 3) * 8;
    auto fill = [&](int st, int c) {
        unsigned int sa = sb + st * 5120u + (unsigned int)(frow * 80 + fseg * 2);
        size_t ga = (size_t)(m0 + frow) * 1024 + c * 32 + fseg;
        size_t gb = (size_t)(n0 + frow) * 1024 + c * 32 + fseg;
        cpa16(sa + D_AH, Agh + ga);
        cpa16(sa + D_AL, Agl + ga);
        cpa16(sa + D_BH, Bgh + gb);
        cpa16(sa + D_BL, Bgl + gb);
        asm volatile("cp.async.commit_group;");
    };

    fill(0, 0); fill(1, 1);
    for (int c = 0; c < 32; c++) {
        asm volatile("cp.async.wait_group 1;");
        __syncthreads();
        if (c + 2 < 32) fill((c + 2) % 3, c + 2);
        else asm volatile("cp.async.commit_group;");

        const int st = c % 3;
        const unsigned int aH = sb + st * 5120u + D_AH + aoff;
        const unsigned int aL = sb + st * 5120u + D_AL + aoff;
        const unsigned int bH = sb + st * 5120u + D_BH + boff;
        const unsigned int bL = sb + st * 5120u + D_BL + boff;

        unsigned int ah[2][2][4], al[2][2][4], bh[2][2][2], bl[2][2][2];
        auto load_frags = [&](int buf, int kb) {
#pragma unroll
            for (int mb = 0; mb < 2; mb++) {
                ldm4(ah[buf][mb], aH + mb * 1280u + kb * 2);
                ldm4(al[buf][mb], aL + mb * 1280u + kb * 2);
            }
            unsigned int tmp[4];
            ldm4(tmp, bH + kb * 2);
            bh[buf][0][0] = tmp[0]; bh[buf][0][1] = tmp[1];
            bh[buf][1][0] = tmp[2]; bh[buf][1][1] = tmp[3];
            ldm4(tmp, bL + kb * 2);
            bl[buf][0][0] = tmp[0]; bl[buf][0][1] = tmp[1];
            bl[buf][1][0] = tmp[2]; bl[buf][1][1] = tmp[3];
        };
        load_frags(0, 0);
#pragma unroll
        for (int kh = 0; kh < 2; kh++) {
            if (kh == 0) load_frags(1, 16);
#pragma unroll
            for (int nb = 0; nb < 2; nb++) {
                mma16(acc[0][nb], ah[kh][0], bh[kh][nb]);
                mma16(acc[1][nb], ah[kh][1], bh[kh][nb]);
            }
#pragma unroll
            for (int nb = 0; nb < 2; nb++) {
                mma16(acc[0][nb], al[kh][0], bh[kh][nb]);
                mma16(acc[1][nb], al[kh][1], bh[kh][nb]);
            }
#pragma unroll
            for (int nb = 0; nb < 2; nb++) {
                mma16(acc[0][nb], ah[kh][0], bl[kh][nb]);
                mma16(acc[1][nb], ah[kh][1], bl[kh][nb]);
            }
        }
        __syncthreads();    // stage consumed; safe for refill next iteration
    }
    asm volatile("cp.async.wait_group 0;");

#pragma unroll
    for (int mb = 0; mb < 2; mb++)
#pragma unroll
        for (int nb = 0; nb < 2; nb++) {
            int rwb = m0 + wm * 32 + mb * 16 + r;
            int cwb = n0 + wn * 16 + nb * 8 + 2 * q;
#pragma unroll
            for (int e = 0; e < 4; e++) {
                int rr = rwb + (e >> 1) * 8;
                int cc = cwb + (e & 1);
                float v = acc[mb][nb][e] + bias[cc];
                if (SRC == 0) {
                    v = fmaxf(v, 0.f);
                    size_t o = (size_t)rr * 1024 + cc;
                    split_bf(v, g_t1h[o], g_t1l[o]);
                } else {
                    int tt = rr >> 8, bb = rr & 255;   // row = t*256 + b
                    outp[((size_t)bb * Tt + tt) * Ff + cc] = v;
                }
            }
        }
}

// ---------------- launch ------------------------------------------------------
extern "C" void kernel_launch(void* const* d_in, const int* in_sizes, int n_in,
                              void* d_out, int out_size) {
    const float* x   = (const float*)d_in[0];
    const float* ewx = (const float*)d_in[1];
    const float* ewh = (const float*)d_in[2];
    const float* eb  = (const float*)d_in[3];
    const float* dwx = (const float*)d_in[4];
    const float* dwh = (const float*)d_in[5];
    const float* db  = (const float*)d_in[6];
    const float* d1w = (const float*)d_in[7];
    const float* d1b = (const float*)d_in[8];
    const float* d2w = (const float*)d_in[9];
    const float* d2b = (const float*)d_in[10];
    float* out = (float*)d_out;

    cudaFuncSetAttribute(lstm_persist, cudaFuncAttributeMaxDynamicSharedMemorySize,
                         (int)L_TOTAL);
    cudaFuncSetAttribute(dense_kernel<0>, cudaFuncAttributeMaxDynamicSharedMemorySize,
                         (int)D_TOTAL);
    cudaFuncSetAttribute(dense_kernel<1>, cudaFuncAttributeMaxDynamicSharedMemorySize,
                         (int)D_TOTAL);

    prep_kernel<<<(Bb * Tt * Ff + 255) / 256, 256>>>(x, ewx, ewh, dwx, dwh, d1w, d2w);

    dim3 sgrid(Uu / 32, Bb / 64);   // 128 CTAs: single wave on 148 SMs
    lstm_persist<<<sgrid, 512, L_TOTAL>>>(eb, db);

    dense_kernel<0><<<dim3(1024 / 64, (Tt * Bb) / 64), 256, D_TOTAL>>>(d1b, nullptr);
    dense_kernel<1><<<dim3(128 / 64, (Tt * Bb) / 64), 256, D_TOTAL>>>(d2b, out);
}

// round 13
// speedup vs baseline: 1.2513x; 1.1117x over previous
#include <cuda_runtime.h>
#include <cuda_bf16.h>

#define Bb 256
#define Tt 512
#define Ff 128
#define Uu 1024
#define N4 4096

typedef __nv_bfloat16 bf;

// ---------------- scratch (static device globals; no allocation) -------------
__device__ bf g_h0h[Bb * Uu]; __device__ bf g_h0l[Bb * Uu];
__device__ bf g_h1h[Bb * Uu]; __device__ bf g_h1l[Bb * Uu];
__device__ bf g_hsh[(size_t)Tt * Bb * Uu]; __device__ bf g_hsl[(size_t)Tt * Bb * Uu];
__device__ bf g_t1h[(size_t)Tt * Bb * Uu]; __device__ bf g_t1l[(size_t)Tt * Bb * Uu];
__device__ bf g_xh[(size_t)Bb * Tt * Ff];  __device__ bf g_xl[(size_t)Bb * Tt * Ff];
// weights transposed to [n][k] and split hi/lo
__device__ bf g_whTh[(size_t)N4 * Uu]; __device__ bf g_whTl[(size_t)N4 * Uu];
__device__ bf g_wdTh[(size_t)N4 * Uu]; __device__ bf g_wdTl[(size_t)N4 * Uu];
__device__ bf g_wxTh[(size_t)N4 * Ff]; __device__ bf g_wxTl[(size_t)N4 * Ff];
__device__ bf g_d1Th[(size_t)Uu * Uu]; __device__ bf g_d1Tl[(size_t)Uu * Uu];
__device__ bf g_d2Th[(size_t)Ff * Uu]; __device__ bf g_d2Tl[(size_t)Ff * Uu];
__device__ unsigned int g_bar;

// ---------------- helpers ----------------------------------------------------
__device__ __forceinline__ void split_bf(float v, bf& hi, bf& lo) {
    hi = __float2bfloat16_rn(v);
    lo = __float2bfloat16_rn(v - __bfloat162float(hi));
}
__device__ __forceinline__ void mma16(float c[4], const unsigned int a[4],
                                      const unsigned int b[2]) {
    asm volatile(
        "mma.sync.aligned.m16n8k16.row.col.f32.bf16.bf16.f32 "
        "{%0,%1,%2,%3}, {%4,%5,%6,%7}, {%8,%9}, {%0,%1,%2,%3};"
        : "+f"(c[0]), "+f"(c[1]), "+f"(c[2]), "+f"(c[3])
        : "r"(a[0]), "r"(a[1]), "r"(a[2]), "r"(a[3]), "r"(b[0]), "r"(b[1]));
}
__device__ __forceinline__ void ldm4(unsigned int r[4], unsigned int addr) {
    asm volatile("ldmatrix.sync.aligned.m8n8.x4.shared.b16 {%0,%1,%2,%3}, [%4];"
                 : "=r"(r[0]), "=r"(r[1]), "=r"(r[2]), "=r"(r[3]) : "r"(addr));
}
__device__ __forceinline__ float sigmoidf_(float x) {
    return 1.f / (1.f + __expf(-x));
}
__device__ __forceinline__ float tanhfast(float x) {
    // 1 - 2/(e^{2x}+1): exact at +-inf, few-ulp elsewhere (EX2+fast div)
    float t = __expf(2.f * x);
    return 1.f - __fdividef(2.f, t + 1.f);
}
__device__ __forceinline__ void cpa16(unsigned int sa, const void* g) {
    // cg: bypass L1 — required: persistent kernel, h re-read across steps.
    asm volatile("cp.async.cg.shared.global [%0], [%1], 16;" :: "r"(sa), "l"(g));
}

// ---------------- prep: split to bf16 hi/lo, transpose weights ---------------
__global__ void __launch_bounds__(256) prep_kernel(
        const float* __restrict__ x,
        const float* __restrict__ ewx, const float* __restrict__ ewh,
        const float* __restrict__ dwx, const float* __restrict__ dwh,
        const float* __restrict__ d1w, const float* __restrict__ d2w) {
    int i = blockIdx.x * blockDim.x + threadIdx.x;
    if (i == 0) g_bar = 0u;
    if (i < Bb * Tt * Ff) split_bf(x[i], g_xh[i], g_xl[i]);
    if (i < N4 * Uu) {
        int k = i >> 12, n = i & 4095;
        size_t o = (size_t)n * Uu + k;
        split_bf(ewh[i],          g_whTh[o], g_whTl[o]);
        split_bf(dwx[i] + dwh[i], g_wdTh[o], g_wdTl[o]);
    }
    if (i < N4 * Ff) {
        int k = i >> 12, n = i & 4095;
        size_t o = (size_t)n * Ff + k;
        split_bf(ewx[i], g_wxTh[o], g_wxTl[o]);
    }
    if (i < Uu * Uu) {
        int k = i >> 10, n = i & 1023;
        size_t o = (size_t)n * Uu + k;
        split_bf(d1w[i], g_d1Th[o], g_d1Tl[o]);
    }
    if (i < Uu * Ff) {
        int k = i >> 7, n = i & 127;
        size_t o = (size_t)n * Uu + k;
        split_bf(d2w[i], g_d2Th[o], g_d2Tl[o]);
    }
    if (i < Bb * Uu) {
        g_h0h[i] = __float2bfloat16(0.f); g_h0l[i] = __float2bfloat16(0.f);
    }
}

// ---------------- persistent recurrence kernel --------------------------------
// 128 CTAs (32 u-tiles x 4 m-tiles), 512 threads (16 warps: 2m x 8n).
// K=64 chunks (18 enc / 16 dec), 3-stage cp.async ring, bf16x3.
// B columns gate-interleaved: tile col = wn*16 + (g>>1)*8 + ul*2 + (g&1),
// u = u0 + wn*4 + ul  => each thread's accs hold all 4 gates of one (row,u).
// Stage layout (row stride 144B = bank-stagger +4/row, 16B aligned):
//   Ah [64][72]bf @0 (9216B)  Al @9216  Bh [128][72]bf @18432  Bl @36864
#define STG_SZ 55296u
#define L_TOTAL (3u * STG_SZ)   // 165888 B

__device__ __forceinline__ void fill_stage(unsigned int sb, int st,
        const bf* Ah, const bf* Al, size_t lda,
        const bf* Bh, const bf* Bl, size_t ldb, int u0, int tid) {
    unsigned int base = sb + st * STG_SZ;
    {   // A: 64 rows x 8 segs(16B), hi+lo : 512 threads -> 1 each
        int row = tid >> 3, seg = tid & 7;
        unsigned int sa = base + row * 144 + seg * 16;
        cpa16(sa, Ah + (size_t)row * lda + seg * 8);
        cpa16(sa + 9216u, Al + (size_t)row * lda + seg * 8);
    }
#pragma unroll
    for (int s = 0; s < 2; s++) {   // B: 128 rows x 8 segs, hi+lo
        int idx = tid + s * 512;
        int nn = idx >> 3, seg = idx & 7;
        int wn_ = nn >> 4, rem = nn & 15;
        int gate = ((rem >> 3) << 1) | (rem & 1);
        int ul = (rem >> 1) & 3;
        size_t grow = (size_t)((gate << 10) + u0 + wn_ * 4 + ul) * ldb;
        unsigned int sa = base + 18432u + nn * 144 + seg * 16;
        cpa16(sa, Bh + grow + seg * 8);
        cpa16(sa + 18432u, Bl + grow + seg * 8);
    }
    asm volatile("cp.async.commit_group;");
}

__global__ void __launch_bounds__(512) lstm_persist(const float* __restrict__ eb,
                                                    const float* __restrict__ db) {
    extern __shared__ char smraw[];
    const unsigned int sb = (unsigned int)__cvta_generic_to_shared(smraw);
    const int u0 = blockIdx.x * 32;
    const int m0 = blockIdx.y * 64;
    const int tid = threadIdx.x, lane = tid & 31, wid = tid >> 5;
    const int wm = wid >> 3, wn = wid & 7, r = lane >> 2, q = lane & 3;

    // ldmatrix per-lane offsets (row stride 144B)
    const int arow = wm * 32 + (lane & 7) + ((lane >> 3) & 1) * 8;
    const unsigned int aoff = (unsigned int)(arow * 144 + (lane >> 4) * 16);
    const int brow = wn * 16 + (lane & 7) + ((lane >> 4) & 1) * 8;
    const unsigned int boff = (unsigned int)(brow * 144 + ((lane >> 3) & 1) * 16);

    const int my_u = u0 + wn * 4 + q;          // this thread's unit (all 4 gates)
    float b0 = 0.f, b1 = 0.f, b2 = 0.f, b3 = 0.f;  // gate biases (per phase)

    float c_reg[4];                            // c for (mb,rh) in {0,1}^2
#pragma unroll
    for (int s = 0; s < 4; s++) c_reg[s] = 0.f;

    for (int t = 0; t < 2 * Tt; t++) {
        const int is_dec = (t >= Tt);
        const bf *hih, *hil; bf *hoh, *hol;
        const bf *Wh, *Wl;
        int NC, ts;
        if (is_dec) {
            ts = t - Tt;
            Wh = g_wdTh; Wl = g_wdTl; NC = 16;
            if (ts == 0) { hih = g_h0h; hil = g_h0l; }
            else { hih = g_hsh + (size_t)(ts - 1) * Bb * Uu;
                   hil = g_hsl + (size_t)(ts - 1) * Bb * Uu; }
            hoh = g_hsh + (size_t)ts * Bb * Uu;
            hol = g_hsl + (size_t)ts * Bb * Uu;
        } else {
            ts = t;
            Wh = g_whTh; Wl = g_whTl; NC = 18;  // 16 h + 2 x chunks
            if (ts & 1) { hih = g_h1h; hil = g_h1l; hoh = g_h0h; hol = g_h0l; }
            else        { hih = g_h0h; hil = g_h0l; hoh = g_h1h; hol = g_h1l; }
        }
        if (t == 0 || t == Tt) {               // preload gate biases for phase
            const float* bs = is_dec ? db : eb;
            b0 = bs[my_u]; b1 = bs[my_u + 1024];
            b2 = bs[my_u + 2048]; b3 = bs[my_u + 3072];
        }

        float acc[2][2][4];
#pragma unroll
        for (int a = 0; a < 2; a++)
#pragma unroll
            for (int b = 0; b < 2; b++)
#pragma unroll
                for (int e = 0; e < 4; e++) acc[a][b][e] = 0.f;

        auto getAB = [&](int c, const bf*& Ah_, const bf*& Al_, size_t& lda,
                         const bf*& Bh_, const bf*& Bl_, size_t& ldb) {
            if (c < 16) {
                Ah_ = hih + (size_t)m0 * Uu + c * 64;
                Al_ = hil + (size_t)m0 * Uu + c * 64;
                lda = Uu;
                Bh_ = Wh + c * 64; Bl_ = Wl + c * 64; ldb = Uu;
            } else {
                int cc = c - 16;
                size_t off = (size_t)m0 * (Tt * Ff) + (size_t)ts * Ff + cc * 64;
                Ah_ = g_xh + off; Al_ = g_xl + off; lda = (size_t)Tt * Ff;
                Bh_ = g_wxTh + cc * 64; Bl_ = g_wxTl + cc * 64; ldb = Ff;
            }
        };

        // prologue: fill 2 stages
#pragma unroll
        for (int p = 0; p < 2; p++) {
            const bf *Ah_, *Al_, *Bh_, *Bl_; size_t lda, ldb;
            getAB(p, Ah_, Al_, lda, Bh_, Bl_, ldb);
            fill_stage(sb, p, Ah_, Al_, lda, Bh_, Bl_, ldb, u0, tid);
        }

        for (int c = 0; c < NC; c++) {
            asm volatile("cp.async.wait_group 1;");   // group c complete
            __syncthreads();                          // all warps done chunk c-1
            if (c + 2 < NC) {
                const bf *Ah_, *Al_, *Bh_, *Bl_; size_t lda, ldb;
                getAB(c + 2, Ah_, Al_, lda, Bh_, Bl_, ldb);
                int st2 = (c + 2) % 3;
                fill_stage(sb, st2, Ah_, Al_, lda, Bh_, Bl_, ldb, u0, tid);
            } else {
                asm volatile("cp.async.commit_group;");   // keep group==chunk
            }
            const int st = c % 3;
            const unsigned int base = sb + st * STG_SZ;
            const unsigned int aH = base + aoff;
            const unsigned int aL = base + 9216u + aoff;
            const unsigned int bH = base + 18432u + boff;
            const unsigned int bL = base + 36864u + boff;

#pragma unroll
            for (int kh = 0; kh < 4; kh++) {
                const unsigned int kb = kh * 32;   // bytes: 16 halves per kh
                unsigned int ah[2][4], al[2][4], bh[2][2], bl[2][2];
#pragma unroll
                for (int mb = 0; mb < 2; mb++) {
                    ldm4(ah[mb], aH + mb * 2304u + kb);
                    ldm4(al[mb], aL + mb * 2304u + kb);
                }
                {
                    unsigned int tmp[4];
                    ldm4(tmp, bH + kb);
                    bh[0][0] = tmp[0]; bh[0][1] = tmp[1];
                    bh[1][0] = tmp[2]; bh[1][1] = tmp[3];
                    ldm4(tmp, bL + kb);
                    bl[0][0] = tmp[0]; bl[0][1] = tmp[1];
                    bl[1][0] = tmp[2]; bl[1][1] = tmp[3];
                }
                // per-accumulator order hh,lh,hl — numerics identical
#pragma unroll
                for (int nb = 0; nb < 2; nb++) {
                    mma16(acc[0][nb], ah[0], bh[nb]);
                    mma16(acc[1][nb], ah[1], bh[nb]);
                }
#pragma unroll
                for (int nb = 0; nb < 2; nb++) {
                    mma16(acc[0][nb], al[0], bh[nb]);
                    mma16(acc[1][nb], al[1], bh[nb]);
                }
#pragma unroll
                for (int nb = 0; nb < 2; nb++) {
                    mma16(acc[0][nb], ah[0], bl[nb]);
                    mma16(acc[1][nb], ah[1], bl[nb]);
                }
            }
        }
        asm volatile("cp.async.wait_group 0;");
        __syncthreads();        // all mma done; stages free (hst aliases stage 0)

        // cell math straight from accumulators (gates live in this thread)
        bf* hsth = (bf*)smraw;                  // [64][32] hi   (4 KB)
        bf* hstl = (bf*)(smraw + 4096);         // [64][32] lo   (4 KB)
#pragma unroll
        for (int mb = 0; mb < 2; mb++)
#pragma unroll
            for (int rh = 0; rh < 2; rh++) {
                int e0 = rh * 2;
                float zi = acc[mb][0][e0    ] + b0;
                float zf = acc[mb][0][e0 + 1] + b1;
                float zg = acc[mb][1][e0    ] + b2;
                float zo = acc[mb][1][e0 + 1] + b3;
                float ig = sigmoidf_(zi);
                float fg = sigmoidf_(zf);
                float gg = tanhfast(zg);
                float og = sigmoidf_(zo);
                int ci = mb * 2 + rh;
                float cn = fg * c_reg[ci] + ig * gg;
                c_reg[ci] = cn;
                float h = og * tanhfast(cn);
                int row = wm * 32 + mb * 16 + r + rh * 8;
                int uc = wn * 4 + q;
                split_bf(h, hsth[row * 32 + uc], hstl[row * 32 + uc]);
            }
        __syncthreads();
        {   // cooperative coalesced h store: 64 rows x 32 u, hi+lo (4KB each)
            if (tid < 256) {
                int row = tid >> 2, sg = tid & 3;
                *(uint4*)(hoh + (size_t)(m0 + row) * Uu + u0 + sg * 8) =
                    *(const uint4*)(smraw + row * 64 + sg * 16);
            } else {
                int t2 = tid - 256;
                int row = t2 >> 2, sg = t2 & 3;
                *(uint4*)(hol + (size_t)(m0 + row) * Uu + u0 + sg * 8) =
                    *(const uint4*)(smraw + 4096 + row * 64 + sg * 16);
            }
        }

        // -------- grid barrier: 128 CTAs all co-resident (1 wave on 148 SMs) --
        __syncthreads();
        if (tid == 0) {
            __threadfence();
            atomicAdd(&g_bar, 1u);
            unsigned int target = 128u * (unsigned int)(t + 1);
            while (*((volatile unsigned int*)&g_bar) < target) {}
            __threadfence();
        }
        __syncthreads();
    }
}

// ---------------- dense epilogue GEMMs (bf16x3, ldmatrix + cp.async ring) -----
#define D_AH 0u
#define D_AL 15360u
#define D_BH 30720u
#define D_BL 46080u
#define D_TOTAL 61440u

template <int SRC>
__global__ void __launch_bounds__(256) dense_kernel(const float* __restrict__ bias,
                                                    float* __restrict__ outp) {
    const bf* Agh = (SRC == 0) ? g_hsh : g_t1h;
    const bf* Agl = (SRC == 0) ? g_hsl : g_t1l;
    const bf* Bgh = (SRC == 0) ? g_d1Th : g_d2Th;
    const bf* Bgl = (SRC == 0) ? g_d1Tl : g_d2Tl;
    extern __shared__ char smraw[];
    const unsigned int sb = (unsigned int)__cvta_generic_to_shared(smraw);
    const int n0 = blockIdx.x * 64;
    const int m0 = blockIdx.y * 64;
    const int tid = threadIdx.x, lane = tid & 31, wid = tid >> 5;
    const int wm = wid >> 2, wn = wid & 3, r = lane >> 2, q = lane & 3;

    const int arow = wm * 32 + (lane & 7) + ((lane >> 3) & 1) * 8;
    const unsigned int aoff = (unsigned int)(arow * 80 + (lane >> 4) * 16);
    const int brow = wn * 16 + (lane & 7) + ((lane >> 4) & 1) * 8;
    const unsigned int boff = (unsigned int)(brow * 80 + ((lane >> 3) & 1) * 16);

    float acc[2][2][4];
#pragma unroll
    for (int a = 0; a < 2; a++)
#pragma unroll
        for (int b = 0; b < 2; b++)
#pragma unroll
            for (int e = 0; e < 4; e++) acc[a][b][e] = 0.f;

    const int frow = tid >> 2, fseg = (tid & 3) * 8;
    auto fill = [&](int st, int c) {
        unsigned int sa = sb + st * 5120u + (unsigned int)(frow * 80 + fseg * 2);
        size_t ga = (size_t)(m0 + frow) * 1024 + c * 32 + fseg;
        size_t gb = (size_t)(n0 + frow) * 1024 + c * 32 + fseg;
        cpa16(sa + D_AH, Agh + ga);
        cpa16(sa + D_AL, Agl + ga);
        cpa16(sa + D_BH, Bgh + gb);
        cpa16(sa + D_BL, Bgl + gb);
        asm volatile("cp.async.commit_group;");
    };

    fill(0, 0); fill(1, 1);
    for (int c = 0; c < 32; c++) {
        asm volatile("cp.async.wait_group 1;");
        __syncthreads();
        if (c + 2 < 32) fill((c + 2) % 3, c + 2);
        else asm volatile("cp.async.commit_group;");

        const int st = c % 3;
        const unsigned int aH = sb + st * 5120u + D_AH + aoff;
        const unsigned int aL = sb + st * 5120u + D_AL + aoff;
        const unsigned int bH = sb + st * 5120u + D_BH + boff;
        const unsigned int bL = sb + st * 5120u + D_BL + boff;

        unsigned int ah[2][2][4], al[2][2][4], bh[2][2][2], bl[2][2][2];
        auto load_frags = [&](int buf, int kb) {
#pragma unroll
            for (int mb = 0; mb < 2; mb++) {
                ldm4(ah[buf][mb], aH + mb * 1280u + kb * 2);
                ldm4(al[buf][mb], aL + mb * 1280u + kb * 2);
            }
            unsigned int tmp[4];
            ldm4(tmp, bH + kb * 2);
            bh[buf][0][0] = tmp[0]; bh[buf][0][1] = tmp[1];
            bh[buf][1][0] = tmp[2]; bh[buf][1][1] = tmp[3];
            ldm4(tmp, bL + kb * 2);
            bl[buf][0][0] = tmp[0]; bl[buf][0][1] = tmp[1];
            bl[buf][1][0] = tmp[2]; bl[buf][1][1] = tmp[3];
        };
        load_frags(0, 0);
#pragma unroll
        for (int kh = 0; kh < 2; kh++) {
            if (kh == 0) load_frags(1, 16);
#pragma unroll
            for (int nb = 0; nb < 2; nb++) {
                mma16(acc[0][nb], ah[kh][0], bh[kh][nb]);
                mma16(acc[1][nb], ah[kh][1], bh[kh][nb]);
            }
#pragma unroll
            for (int nb = 0; nb < 2; nb++) {
                mma16(acc[0][nb], al[kh][0], bh[kh][nb]);
                mma16(acc[1][nb], al[kh][1], bh[kh][nb]);
            }
#pragma unroll
            for (int nb = 0; nb < 2; nb++) {
                mma16(acc[0][nb], ah[kh][0], bl[kh][nb]);
                mma16(acc[1][nb], ah[kh][1], bl[kh][nb]);
            }
        }
        __syncthreads();
    }
    asm volatile("cp.async.wait_group 0;");

#pragma unroll
    for (int mb = 0; mb < 2; mb++)
#pragma unroll
        for (int nb = 0; nb < 2; nb++) {
            int rwb = m0 + wm * 32 + mb * 16 + r;
            int cwb = n0 + wn * 16 + nb * 8 + 2 * q;
#pragma unroll
            for (int e = 0; e < 4; e++) {
                int rr = rwb + (e >> 1) * 8;
                int cc = cwb + (e & 1);
                float v = acc[mb][nb][e] + bias[cc];
                if (SRC == 0) {
                    v = fmaxf(v, 0.f);
                    size_t o = (size_t)rr * 1024 + cc;
                    split_bf(v, g_t1h[o], g_t1l[o]);
                } else {
                    int tt = rr >> 8, bb = rr & 255;   // row = t*256 + b
                    outp[((size_t)bb * Tt + tt) * Ff + cc] = v;
                }
            }
        }
}

// ---------------- launch ------------------------------------------------------
extern "C" void kernel_launch(void* const* d_in, const int* in_sizes, int n_in,
                              void* d_out, int out_size) {
    const float* x   = (const float*)d_in[0];
    const float* ewx = (const float*)d_in[1];
    const float* ewh = (const float*)d_in[2];
    const float* eb  = (const float*)d_in[3];
    const float* dwx = (const float*)d_in[4];
    const float* dwh = (const float*)d_in[5];
    const float* db  = (const float*)d_in[6];
    const float* d1w = (const float*)d_in[7];
    const float* d1b = (const float*)d_in[8];
    const float* d2w = (const float*)d_in[9];
    const float* d2b = (const float*)d_in[10];
    float* out = (float*)d_out;

    cudaFuncSetAttribute(lstm_persist, cudaFuncAttributeMaxDynamicSharedMemorySize,
                         (int)L_TOTAL);
    cudaFuncSetAttribute(dense_kernel<0>, cudaFuncAttributeMaxDynamicSharedMemorySize,
                         (int)D_TOTAL);
    cudaFuncSetAttribute(dense_kernel<1>, cudaFuncAttributeMaxDynamicSharedMemorySize,
                         (int)D_TOTAL);

    prep_kernel<<<(Bb * Tt * Ff + 255) / 256, 256>>>(x, ewx, ewh, dwx, dwh, d1w, d2w);

    dim3 sgrid(Uu / 32, Bb / 64);   // 128 CTAs: single wave on 148 SMs
    lstm_persist<<<sgrid, 512, L_TOTAL>>>(eb, db);

    dense_kernel<0><<<dim3(1024 / 64, (Tt * Bb) / 64), 256, D_TOTAL>>>(d1b, nullptr);
    dense_kernel<1><<<dim3(128 / 64, (Tt * Bb) / 64), 256, D_TOTAL>>>(d2b, out);
}

// round 14
// speedup vs baseline: 1.3397x; 1.0706x over previous
#include <cuda_runtime.h>
#include <cuda_bf16.h>

#define Bb 256
#define Tt 512
#define Ff 128
#define Uu 1024
#define N4 4096

typedef __nv_bfloat16 bf;

// ---------------- scratch (static device globals; no allocation) -------------
__device__ bf g_h0h[Bb * Uu]; __device__ bf g_h0l[Bb * Uu];
__device__ bf g_h1h[Bb * Uu]; __device__ bf g_h1l[Bb * Uu];
__device__ bf g_hsh[(size_t)Tt * Bb * Uu]; __device__ bf g_hsl[(size_t)Tt * Bb * Uu];
__device__ bf g_t1h[(size_t)Tt * Bb * Uu]; __device__ bf g_t1l[(size_t)Tt * Bb * Uu];
__device__ bf g_xh[(size_t)Bb * Tt * Ff];  __device__ bf g_xl[(size_t)Bb * Tt * Ff];
// weights transposed to [n][k] and split hi/lo
__device__ bf g_whTh[(size_t)N4 * Uu]; __device__ bf g_whTl[(size_t)N4 * Uu];
__device__ bf g_wdTh[(size_t)N4 * Uu]; __device__ bf g_wdTl[(size_t)N4 * Uu];
__device__ bf g_wxTh[(size_t)N4 * Ff]; __device__ bf g_wxTl[(size_t)N4 * Ff];
__device__ bf g_d1Th[(size_t)Uu * Uu]; __device__ bf g_d1Tl[(size_t)Uu * Uu];
__device__ bf g_d2Th[(size_t)Ff * Uu]; __device__ bf g_d2Tl[(size_t)Ff * Uu];
__device__ unsigned int g_bar;

// ---------------- helpers ----------------------------------------------------
__device__ __forceinline__ void split_bf(float v, bf& hi, bf& lo) {
    hi = __float2bfloat16_rn(v);
    lo = __float2bfloat16_rn(v - __bfloat162float(hi));
}
__device__ __forceinline__ void mma16(float c[4], const unsigned int a[4],
                                      const unsigned int b[2]) {
    asm volatile(
        "mma.sync.aligned.m16n8k16.row.col.f32.bf16.bf16.f32 "
        "{%0,%1,%2,%3}, {%4,%5,%6,%7}, {%8,%9}, {%0,%1,%2,%3};"
        : "+f"(c[0]), "+f"(c[1]), "+f"(c[2]), "+f"(c[3])
        : "r"(a[0]), "r"(a[1]), "r"(a[2]), "r"(a[3]), "r"(b[0]), "r"(b[1]));
}
__device__ __forceinline__ void ldm4(unsigned int r[4], unsigned int addr) {
    asm volatile("ldmatrix.sync.aligned.m8n8.x4.shared.b16 {%0,%1,%2,%3}, [%4];"
                 : "=r"(r[0]), "=r"(r[1]), "=r"(r[2]), "=r"(r[3]) : "r"(addr));
}
__device__ __forceinline__ float sigmoidf_(float x) {
    return 1.f / (1.f + __expf(-x));
}
__device__ __forceinline__ float tanhfast(float x) {
    float t = __expf(2.f * x);
    return 1.f - __fdividef(2.f, t + 1.f);
}
__device__ __forceinline__ void cpa16(unsigned int sa, const void* g) {
    // cg: bypass L1 — required: persistent kernel, h re-read across steps.
    asm volatile("cp.async.cg.shared.global [%0], [%1], 16;" :: "r"(sa), "l"(g));
}

// ---------------- prep: split to bf16 hi/lo, transpose weights ---------------
__global__ void __launch_bounds__(256) prep_kernel(
        const float* __restrict__ x,
        const float* __restrict__ ewx, const float* __restrict__ ewh,
        const float* __restrict__ dwx, const float* __restrict__ dwh,
        const float* __restrict__ d1w, const float* __restrict__ d2w) {
    int i = blockIdx.x * blockDim.x + threadIdx.x;
    if (i == 0) g_bar = 0u;
    if (i < Bb * Tt * Ff) split_bf(x[i], g_xh[i], g_xl[i]);
    if (i < N4 * Uu) {
        int k = i >> 12, n = i & 4095;
        size_t o = (size_t)n * Uu + k;
        split_bf(ewh[i],          g_whTh[o], g_whTl[o]);
        split_bf(dwx[i] + dwh[i], g_wdTh[o], g_wdTl[o]);
    }
    if (i < N4 * Ff) {
        int k = i >> 12, n = i & 4095;
        size_t o = (size_t)n * Ff + k;
        split_bf(ewx[i], g_wxTh[o], g_wxTl[o]);
    }
    if (i < Uu * Uu) {
        int k = i >> 10, n = i & 1023;
        size_t o = (size_t)n * Uu + k;
        split_bf(d1w[i], g_d1Th[o], g_d1Tl[o]);
    }
    if (i < Uu * Ff) {
        int k = i >> 7, n = i & 127;
        size_t o = (size_t)n * Uu + k;
        split_bf(d2w[i], g_d2Th[o], g_d2Tl[o]);
    }
    if (i < Bb * Uu) {
        g_h0h[i] = __float2bfloat16(0.f); g_h0l[i] = __float2bfloat16(0.f);
    }
}

// ---------------- persistent recurrence kernel --------------------------------
// 128 CTAs (32 u-tiles x 4 m-tiles), 512 threads (16 warps: 2m x 8n).
// K=64 chunks, 3-stage ring, bf16x3, gate-interleaved B columns.
// NEW: encoder chunk order = [x0, x1, h0..h15]; x chunks computed BEFORE the
// grid-barrier wait (x/Wx static). Decoder prefills B (weights) of chunks 0,1
// pre-barrier. Barrier latency + refill bubble hide behind h-independent work.
// Stage layout (row stride 144B): Ah@0 Al@9216 Bh@18432 Bl@36864
#define STG_SZ 55296u
#define L_TOTAL (3u * STG_SZ)   // 165888 B

__device__ __forceinline__ void fill_A(unsigned int sb, int st,
        const bf* Ah, const bf* Al, size_t lda, int tid) {
    unsigned int base = sb + st * STG_SZ;
    int row = tid >> 3, seg = tid & 7;
    unsigned int sa = base + row * 144 + seg * 16;
    cpa16(sa, Ah + (size_t)row * lda + seg * 8);
    cpa16(sa + 9216u, Al + (size_t)row * lda + seg * 8);
}
__device__ __forceinline__ void fill_B(unsigned int sb, int st,
        const bf* Bh, const bf* Bl, size_t ldb, int u0, int tid) {
    unsigned int base = sb + st * STG_SZ + 18432u;
#pragma unroll
    for (int s = 0; s < 2; s++) {
        int idx = tid + s * 512;
        int nn = idx >> 3, seg = idx & 7;
        int wn_ = nn >> 4, rem = nn & 15;
        int gate = ((rem >> 3) << 1) | (rem & 1);
        int ul = (rem >> 1) & 3;
        size_t grow = (size_t)((gate << 10) + u0 + wn_ * 4 + ul) * ldb;
        unsigned int sa = base + nn * 144 + seg * 16;
        cpa16(sa, Bh + grow + seg * 8);
        cpa16(sa + 18432u, Bl + grow + seg * 8);
    }
}
#define COMMIT() asm volatile("cp.async.commit_group;")

__global__ void __launch_bounds__(512) lstm_persist(const float* __restrict__ eb,
                                                    const float* __restrict__ db) {
    extern __shared__ char smraw[];
    const unsigned int sb = (unsigned int)__cvta_generic_to_shared(smraw);
    const int u0 = blockIdx.x * 32;
    const int m0 = blockIdx.y * 64;
    const int tid = threadIdx.x, lane = tid & 31, wid = tid >> 5;
    const int wm = wid >> 3, wn = wid & 7, r = lane >> 2, q = lane & 3;

    const int arow = wm * 32 + (lane & 7) + ((lane >> 3) & 1) * 8;
    const unsigned int aoff = (unsigned int)(arow * 144 + (lane >> 4) * 16);
    const int brow = wn * 16 + (lane & 7) + ((lane >> 4) & 1) * 8;
    const unsigned int boff = (unsigned int)(brow * 144 + ((lane >> 3) & 1) * 16);

    const int my_u = u0 + wn * 4 + q;
    float b0 = 0.f, b1 = 0.f, b2 = 0.f, b3 = 0.f;

    float c_reg[4];
#pragma unroll
    for (int s = 0; s < 4; s++) c_reg[s] = 0.f;

    // prefill chunks 0,1 of step tn (encoder: full x chunks; decoder: B only)
    auto prefill01 = [&](int tn) {
        if (tn >= 2 * Tt) return;
        if (tn < Tt) {
            size_t xoff = (size_t)m0 * (Tt * Ff) + (size_t)tn * Ff;
#pragma unroll
            for (int p = 0; p < 2; p++) {
                fill_A(sb, p, g_xh + xoff + p * 64, g_xl + xoff + p * 64,
                       (size_t)Tt * Ff, tid);
                fill_B(sb, p, g_wxTh + p * 64, g_wxTl + p * 64, (size_t)Ff, u0, tid);
                COMMIT();
            }
        } else {
#pragma unroll
            for (int p = 0; p < 2; p++) {
                fill_B(sb, p, g_wdTh + p * 64, g_wdTl + p * 64, (size_t)Uu, u0, tid);
                COMMIT();
            }
        }
    };

    prefill01(0);

    for (int t = 0; t < 2 * Tt; t++) {
        const int is_dec = (t >= Tt);
        const bf *hih, *hil; bf *hoh, *hol;
        const bf *Wh, *Wl;
        int NC, ts;
        if (is_dec) {
            ts = t - Tt;
            Wh = g_wdTh; Wl = g_wdTl; NC = 16;        // all h chunks
            if (ts == 0) { hih = g_h0h; hil = g_h0l; }
            else { hih = g_hsh + (size_t)(ts - 1) * Bb * Uu;
                   hil = g_hsl + (size_t)(ts - 1) * Bb * Uu; }
            hoh = g_hsh + (size_t)ts * Bb * Uu;
            hol = g_hsl + (size_t)ts * Bb * Uu;
        } else {
            ts = t;
            Wh = g_whTh; Wl = g_whTl; NC = 18;        // 2 x chunks + 16 h chunks
            if (ts & 1) { hih = g_h1h; hil = g_h1l; hoh = g_h0h; hol = g_h0l; }
            else        { hih = g_h0h; hil = g_h0l; hoh = g_h1h; hol = g_h1l; }
        }
        if (t == 0 || t == Tt) {
            const float* bs = is_dec ? db : eb;
            b0 = bs[my_u]; b1 = bs[my_u + 1024];
            b2 = bs[my_u + 2048]; b3 = bs[my_u + 3072];
        }

        float acc[2][2][4];
#pragma unroll
        for (int a = 0; a < 2; a++)
#pragma unroll
            for (int b = 0; b < 2; b++)
#pragma unroll
                for (int e = 0; e < 4; e++) acc[a][b][e] = 0.f;

        // mma over stage (c % 3)
        auto mma_chunk = [&](int c) {
            const unsigned int base = sb + (c % 3) * STG_SZ;
            const unsigned int aH = base + aoff;
            const unsigned int aL = base + 9216u + aoff;
            const unsigned int bH = base + 18432u + boff;
            const unsigned int bL = base + 36864u + boff;
#pragma unroll
            for (int kh = 0; kh < 4; kh++) {
                const unsigned int kb = kh * 32;
                unsigned int ah[2][4], al[2][4], bh[2][2], bl[2][2];
#pragma unroll
                for (int mb = 0; mb < 2; mb++) {
                    ldm4(ah[mb], aH + mb * 2304u + kb);
                    ldm4(al[mb], aL + mb * 2304u + kb);
                }
                {
                    unsigned int tmp[4];
                    ldm4(tmp, bH + kb);
                    bh[0][0] = tmp[0]; bh[0][1] = tmp[1];
                    bh[1][0] = tmp[2]; bh[1][1] = tmp[3];
                    ldm4(tmp, bL + kb);
                    bl[0][0] = tmp[0]; bl[0][1] = tmp[1];
                    bl[1][0] = tmp[2]; bl[1][1] = tmp[3];
                }
#pragma unroll
                for (int nb = 0; nb < 2; nb++) {
                    mma16(acc[0][nb], ah[0], bh[nb]);
                    mma16(acc[1][nb], ah[1], bh[nb]);
                }
#pragma unroll
                for (int nb = 0; nb < 2; nb++) {
                    mma16(acc[0][nb], al[0], bh[nb]);
                    mma16(acc[1][nb], al[1], bh[nb]);
                }
#pragma unroll
                for (int nb = 0; nb < 2; nb++) {
                    mma16(acc[0][nb], ah[0], bl[nb]);
                    mma16(acc[1][nb], ah[1], bl[nb]);
                }
            }
        };

        // h-chunk source (encoder: chunk c>=2 maps to h block c-2)
        auto fill_h_chunk = [&](int c) {
            int hc = is_dec ? c : (c - 2);
            fill_A(sb, c % 3, hih + (size_t)m0 * Uu + hc * 64,
                   hil + (size_t)m0 * Uu + hc * 64, (size_t)Uu, tid);
            fill_B(sb, c % 3, Wh + hc * 64, Wl + hc * 64, (size_t)Uu, u0, tid);
            COMMIT();
        };

        int cstart;
        if (!is_dec) {
            // ---- x chunks 0,1: computed BEFORE waiting on the grid barrier ----
            asm volatile("cp.async.wait_group 1;");
            __syncthreads();
            mma_chunk(0);
            asm volatile("cp.async.wait_group 0;");
            __syncthreads();
            mma_chunk(1);
            // ---- barrier wait: h(t-1) now needed ----
            if (tid == 0) {
                unsigned int target = 128u * (unsigned int)t;
                while (*((volatile unsigned int*)&g_bar) < target) {}
            }
            __syncthreads();
            fill_h_chunk(2);
            fill_h_chunk(3);
            cstart = 2;
        } else {
            if (tid == 0) {
                unsigned int target = 128u * (unsigned int)t;
                while (*((volatile unsigned int*)&g_bar) < target) {}
            }
            __syncthreads();
            // B of chunks 0,1 prefilled; add the h-dependent A halves
            fill_A(sb, 0, hih + (size_t)m0 * Uu, hil + (size_t)m0 * Uu,
                   (size_t)Uu, tid);
            COMMIT();
            fill_A(sb, 1, hih + (size_t)m0 * Uu + 64, hil + (size_t)m0 * Uu + 64,
                   (size_t)Uu, tid);
            COMMIT();
            cstart = 0;
        }

        for (int c = cstart; c < NC; c++) {
            asm volatile("cp.async.wait_group 1;");
            __syncthreads();
            if (c + 2 < NC) fill_h_chunk(c + 2);
            else COMMIT();                    // keep group==slot (FIFO retire)
            mma_chunk(c);
        }
        asm volatile("cp.async.wait_group 0;");
        __syncthreads();       // all mma done; stage 0 free for h staging

        // cell math straight from accumulators
        bf* hsth = (bf*)smraw;                  // [64][32] hi (4 KB)
        bf* hstl = (bf*)(smraw + 4096);         // [64][32] lo (4 KB)
#pragma unroll
        for (int mb = 0; mb < 2; mb++)
#pragma unroll
            for (int rh = 0; rh < 2; rh++) {
                int e0 = rh * 2;
                float zi = acc[mb][0][e0    ] + b0;
                float zf = acc[mb][0][e0 + 1] + b1;
                float zg = acc[mb][1][e0    ] + b2;
                float zo = acc[mb][1][e0 + 1] + b3;
                float ig = sigmoidf_(zi);
                float fg = sigmoidf_(zf);
                float gg = tanhfast(zg);
                float og = sigmoidf_(zo);
                int ci = mb * 2 + rh;
                float cn = fg * c_reg[ci] + ig * gg;
                c_reg[ci] = cn;
                float h = og * tanhfast(cn);
                int row = wm * 32 + mb * 16 + r + rh * 8;
                int uc = wn * 4 + q;
                split_bf(h, hsth[row * 32 + uc], hstl[row * 32 + uc]);
            }
        __syncthreads();
        {   // cooperative coalesced h store
            if (tid < 256) {
                int row = tid >> 2, sg = tid & 3;
                *(uint4*)(hoh + (size_t)(m0 + row) * Uu + u0 + sg * 8) =
                    *(const uint4*)(smraw + row * 64 + sg * 16);
            } else {
                int t2 = tid - 256;
                int row = t2 >> 2, sg = t2 & 3;
                *(uint4*)(hol + (size_t)(m0 + row) * Uu + u0 + sg * 8) =
                    *(const uint4*)(smraw + 4096 + row * 64 + sg * 16);
            }
        }
        __syncthreads();       // h staged reads done; stages writable again
        if (tid == 0) {
            __threadfence();
            atomicAdd(&g_bar, 1u);          // arrive; wait deferred to next iter
        }
        prefill01(t + 1);      // h-independent fills overlap other CTAs' arrival
    }
}

// ---------------- dense epilogue GEMMs (bf16x3, ldmatrix + cp.async ring) -----
#define D_AH 0u
#define D_AL 15360u
#define D_BH 30720u
#define D_BL 46080u
#define D_TOTAL 61440u

template <int SRC>
__global__ void __launch_bounds__(256) dense_kernel(const float* __restrict__ bias,
                                                    float* __restrict__ outp) {
    const bf* Agh = (SRC == 0) ? g_hsh : g_t1h;
    const bf* Agl = (SRC == 0) ? g_hsl : g_t1l;
    const bf* Bgh = (SRC == 0) ? g_d1Th : g_d2Th;
    const bf* Bgl = (SRC == 0) ? g_d1Tl : g_d2Tl;
    extern __shared__ char smraw[];
    const unsigned int sb = (unsigned int)__cvta_generic_to_shared(smraw);
    const int n0 = blockIdx.x * 64;
    const int m0 = blockIdx.y * 64;
    const int tid = threadIdx.x, lane = tid & 31, wid = tid >> 5;
    const int wm = wid >> 2, wn = wid & 3, r = lane >> 2, q = lane & 3;

    const int arow = wm * 32 + (lane & 7) + ((lane >> 3) & 1) * 8;
    const unsigned int aoff = (unsigned int)(arow * 80 + (lane >> 4) * 16);
    const int brow = wn * 16 + (lane & 7) + ((lane >> 4) & 1) * 8;
    const unsigned int boff = (unsigned int)(brow * 80 + ((lane >> 3) & 1) * 16);

    float acc[2][2][4];
#pragma unroll
    for (int a = 0; a < 2; a++)
#pragma unroll
        for (int b = 0; b < 2; b++)
#pragma unroll
            for (int e = 0; e < 4; e++) acc[a][b][e] = 0.f;

    const int frow = tid >> 2, fseg = (tid & 3) * 8;
    auto fill = [&](int st, int c) {
        unsigned int sa = sb + st * 5120u + (unsigned int)(frow * 80 + fseg * 2);
        size_t ga = (size_t)(m0 + frow) * 1024 + c * 32 + fseg;
        size_t gb = (size_t)(n0 + frow) * 1024 + c * 32 + fseg;
        cpa16(sa + D_AH, Agh + ga);
        cpa16(sa + D_AL, Agl + ga);
        cpa16(sa + D_BH, Bgh + gb);
        cpa16(sa + D_BL, Bgl + gb);
        asm volatile("cp.async.commit_group;");
    };

    fill(0, 0); fill(1, 1);
    for (int c = 0; c < 32; c++) {
        asm volatile("cp.async.wait_group 1;");
        __syncthreads();
        if (c + 2 < 32) fill((c + 2) % 3, c + 2);
        else asm volatile("cp.async.commit_group;");

        const int st = c % 3;
        const unsigned int aH = sb + st * 5120u + D_AH + aoff;
        const unsigned int aL = sb + st * 5120u + D_AL + aoff;
        const unsigned int bH = sb + st * 5120u + D_BH + boff;
        const unsigned int bL = sb + st * 5120u + D_BL + boff;

        unsigned int ah[2][2][4], al[2][2][4], bh[2][2][2], bl[2][2][2];
        auto load_frags = [&](int buf, int kb) {
#pragma unroll
            for (int mb = 0; mb < 2; mb++) {
                ldm4(ah[buf][mb], aH + mb * 1280u + kb * 2);
                ldm4(al[buf][mb], aL + mb * 1280u + kb * 2);
            }
            unsigned int tmp[4];
            ldm4(tmp, bH + kb * 2);
            bh[buf][0][0] = tmp[0]; bh[buf][0][1] = tmp[1];
            bh[buf][1][0] = tmp[2]; bh[buf][1][1] = tmp[3];
            ldm4(tmp, bL + kb * 2);
            bl[buf][0][0] = tmp[0]; bl[buf][0][1] = tmp[1];
            bl[buf][1][0] = tmp[2]; bl[buf][1][1] = tmp[3];
        };
        load_frags(0, 0);
#pragma unroll
        for (int kh = 0; kh < 2; kh++) {
            if (kh == 0) load_frags(1, 16);
#pragma unroll
            for (int nb = 0; nb < 2; nb++) {
                mma16(acc[0][nb], ah[kh][0], bh[kh][nb]);
                mma16(acc[1][nb], ah[kh][1], bh[kh][nb]);
            }
#pragma unroll
            for (int nb = 0; nb < 2; nb++) {
                mma16(acc[0][nb], al[kh][0], bh[kh][nb]);
                mma16(acc[1][nb], al[kh][1], bh[kh][nb]);
            }
#pragma unroll
            for (int nb = 0; nb < 2; nb++) {
                mma16(acc[0][nb], ah[kh][0], bl[kh][nb]);
                mma16(acc[1][nb], ah[kh][1], bl[kh][nb]);
            }
        }
        __syncthreads();
    }
    asm volatile("cp.async.wait_group 0;");

#pragma unroll
    for (int mb = 0; mb < 2; mb++)
#pragma unroll
        for (int nb = 0; nb < 2; nb++) {
            int rwb = m0 + wm * 32 + mb * 16 + r;
            int cwb = n0 + wn * 16 + nb * 8 + 2 * q;
#pragma unroll
            for (int e = 0; e < 4; e++) {
                int rr = rwb + (e >> 1) * 8;
                int cc = cwb + (e & 1);
                float v = acc[mb][nb][e] + bias[cc];
                if (SRC == 0) {
                    v = fmaxf(v, 0.f);
                    size_t o = (size_t)rr * 1024 + cc;
                    split_bf(v, g_t1h[o], g_t1l[o]);
                } else {
                    int tt = rr >> 8, bb = rr & 255;   // row = t*256 + b
                    outp[((size_t)bb * Tt + tt) * Ff + cc] = v;
                }
            }
        }
}

// ---------------- launch ------------------------------------------------------
extern "C" void kernel_launch(void* const* d_in, const int* in_sizes, int n_in,
                              void* d_out, int out_size) {
    const float* x   = (const float*)d_in[0];
    const float* ewx = (const float*)d_in[1];
    const float* ewh = (const float*)d_in[2];
    const float* eb  = (const float*)d_in[3];
    const float* dwx = (const float*)d_in[4];
    const float* dwh = (const float*)d_in[5];
    const float* db  = (const float*)d_in[6];
    const float* d1w = (const float*)d_in[7];
    const float* d1b = (const float*)d_in[8];
    const float* d2w = (const float*)d_in[9];
    const float* d2b = (const float*)d_in[10];
    float* out = (float*)d_out;

    cudaFuncSetAttribute(lstm_persist, cudaFuncAttributeMaxDynamicSharedMemorySize,
                         (int)L_TOTAL);
    cudaFuncSetAttribute(dense_kernel<0>, cudaFuncAttributeMaxDynamicSharedMemorySize,
                         (int)D_TOTAL);
    cudaFuncSetAttribute(dense_kernel<1>, cudaFuncAttributeMaxDynamicSharedMemorySize,
                         (int)D_TOTAL);

    prep_kernel<<<(Bb * Tt * Ff + 255) / 256, 256>>>(x, ewx, ewh, dwx, dwh, d1w, d2w);

    dim3 sgrid(Uu / 32, Bb / 64);   // 128 CTAs: single wave on 148 SMs
    lstm_persist<<<sgrid, 512, L_TOTAL>>>(eb, db);

    dense_kernel<0><<<dim3(1024 / 64, (Tt * Bb) / 64), 256, D_TOTAL>>>(d1b, nullptr);
    dense_kernel<1><<<dim3(128 / 64, (Tt * Bb) / 64), 256, D_TOTAL>>>(d2b, out);
}